// round 1
// baseline (speedup 1.0000x reference)
#include <cuda_runtime.h>
#include <math.h>

#define BATCH 2
#define CCH   512
#define NTOK  4096
#define GRP   32
#define CPG   (CCH / GRP)
#define EPSV  1e-6f

// -------- scratch (no allocation allowed; __device__ globals) --------
__device__ float g_hn[(size_t)BATCH * CCH * NTOK];          // groupnorm output  [b, c, n]
__device__ float g_q [(size_t)BATCH * NTOK * CCH];          // [b, n, c]
__device__ float g_k [(size_t)BATCH * NTOK * CCH];
__device__ float g_v [(size_t)BATCH * NTOK * CCH];
__device__ float g_o [(size_t)BATCH * NTOK * CCH];
__device__ float g_s [(size_t)BATCH * NTOK * NTOK];         // attention scores / probs

// ---------------------------------------------------------------
// GroupNorm: one block per (batch, group)
// ---------------------------------------------------------------
__global__ void groupnorm_kernel(const float* __restrict__ x,
                                 const float* __restrict__ w,
                                 const float* __restrict__ b)
{
    const int bg = blockIdx.x;
    const int bb = bg / GRP;
    const int g  = bg % GRP;
    const int NE = CPG * NTOK;
    const size_t base = ((size_t)bb * CCH + (size_t)g * CPG) * NTOK;

    float s = 0.f, ss = 0.f;
    for (int i = threadIdx.x; i < NE; i += blockDim.x) {
        float v = x[base + i];
        s += v; ss += v * v;
    }
    __shared__ float sh[256], sh2[256];
    sh[threadIdx.x] = s; sh2[threadIdx.x] = ss;
    __syncthreads();
    for (int o = 128; o > 0; o >>= 1) {
        if (threadIdx.x < o) {
            sh[threadIdx.x]  += sh[threadIdx.x + o];
            sh2[threadIdx.x] += sh2[threadIdx.x + o];
        }
        __syncthreads();
    }
    const float mu   = sh[0] / (float)NE;
    const float var  = sh2[0] / (float)NE - mu * mu;
    const float rstd = rsqrtf(var + EPSV);

    for (int i = threadIdx.x; i < NE; i += blockDim.x) {
        int c = g * CPG + i / NTOK;
        float v = x[base + i];
        g_hn[base + i] = (v - mu) * rstd * w[c] + b[c];
    }
}

// ---------------------------------------------------------------
// Row softmax over g_s: one block per row (4096 elems, 16/thread in regs)
// ---------------------------------------------------------------
__global__ void softmax_kernel()
{
    const size_t row = blockIdx.x;
    float* p = g_s + row * (size_t)NTOK;
    const int t = threadIdx.x;

    float loc[16];
    float mx = -1e30f;
#pragma unroll
    for (int i = 0; i < 16; i++) {
        loc[i] = p[t + i * 256];
        mx = fmaxf(mx, loc[i]);
    }
    __shared__ float sh[256];
    sh[t] = mx; __syncthreads();
    for (int o = 128; o > 0; o >>= 1) {
        if (t < o) sh[t] = fmaxf(sh[t], sh[t + o]);
        __syncthreads();
    }
    mx = sh[0];
    __syncthreads();

    float sum = 0.f;
#pragma unroll
    for (int i = 0; i < 16; i++) {
        loc[i] = __expf(loc[i] - mx);
        sum += loc[i];
    }
    sh[t] = sum; __syncthreads();
    for (int o = 128; o > 0; o >>= 1) {
        if (t < o) sh[t] += sh[t + o];
        __syncthreads();
    }
    const float inv = 1.0f / sh[0];
#pragma unroll
    for (int i = 0; i < 16; i++)
        p[t + i * 256] = loc[i] * inv;
}

// ---------------------------------------------------------------
// Tiled SGEMM: 128x128x8 tiles, 256 threads, 8x8 per thread.
//   out[m*Nn + n] = scale * sum_k A(m,k) * B(n,k or k,n)  (+ epilogue)
// AL=0: A[m*K+k]    AL=1: A[k*M+m]
// BL=0: B[n*K+k]    BL=1: B[k*Nn+n]
// EPI=0: none  EPI=1: +bias[n]  EPI=2: +bias[m]+resid[m*Nn+n]
// All dims assumed multiples of tile sizes (true for this problem).
// ---------------------------------------------------------------
template<int AL, int BL, int EPI>
__global__ void gemm_kernel(const float* __restrict__ A,
                            const float* __restrict__ B,
                            float* __restrict__ C,
                            int M, int Nn, int K,
                            size_t sA, size_t sB, size_t sC,
                            const float* __restrict__ bias,
                            const float* __restrict__ resid, size_t sR,
                            float scale)
{
    __shared__ __align__(16) float As[8][128];
    __shared__ __align__(16) float Bs[8][128];

    const int bn = blockIdx.x, bm = blockIdx.y, bz = blockIdx.z;
    A += (size_t)bz * sA;
    B += (size_t)bz * sB;
    C += (size_t)bz * sC;

    const int m0 = bm * 128, n0 = bn * 128;
    const int tid = threadIdx.x;
    const int tx = tid % 16, ty = tid / 16;

    float acc[8][8] = {};

    for (int k0 = 0; k0 < K; k0 += 8) {
        if (AL == 0) {
            int m = tid >> 1, kq = (tid & 1) * 4;
            float4 va = *reinterpret_cast<const float4*>(&A[(size_t)(m0 + m) * K + k0 + kq]);
            As[kq + 0][m] = va.x; As[kq + 1][m] = va.y;
            As[kq + 2][m] = va.z; As[kq + 3][m] = va.w;
        } else {
#pragma unroll
            for (int r = 0; r < 4; r++) {
                int idx = tid + r * 256;
                int k = idx >> 7, m = idx & 127;
                As[k][m] = A[(size_t)(k0 + k) * M + m0 + m];
            }
        }
        if (BL == 0) {
            int n = tid >> 1, kq = (tid & 1) * 4;
            float4 vb = *reinterpret_cast<const float4*>(&B[(size_t)(n0 + n) * K + k0 + kq]);
            Bs[kq + 0][n] = vb.x; Bs[kq + 1][n] = vb.y;
            Bs[kq + 2][n] = vb.z; Bs[kq + 3][n] = vb.w;
        } else {
#pragma unroll
            for (int r = 0; r < 4; r++) {
                int idx = tid + r * 256;
                int k = idx >> 7, n = idx & 127;
                Bs[k][n] = B[(size_t)(k0 + k) * Nn + n0 + n];
            }
        }
        __syncthreads();

#pragma unroll
        for (int kk = 0; kk < 8; kk++) {
            float4 a0 = *reinterpret_cast<const float4*>(&As[kk][ty * 8]);
            float4 a1 = *reinterpret_cast<const float4*>(&As[kk][ty * 8 + 4]);
            float4 b0 = *reinterpret_cast<const float4*>(&Bs[kk][tx * 8]);
            float4 b1 = *reinterpret_cast<const float4*>(&Bs[kk][tx * 8 + 4]);
            float av[8] = {a0.x, a0.y, a0.z, a0.w, a1.x, a1.y, a1.z, a1.w};
            float bv[8] = {b0.x, b0.y, b0.z, b0.w, b1.x, b1.y, b1.z, b1.w};
#pragma unroll
            for (int i = 0; i < 8; i++)
#pragma unroll
                for (int j = 0; j < 8; j++)
                    acc[i][j] += av[i] * bv[j];
        }
        __syncthreads();
    }

#pragma unroll
    for (int i = 0; i < 8; i++) {
        const int m = m0 + ty * 8 + i;
#pragma unroll
        for (int j = 0; j < 8; j++) {
            const int n = n0 + tx * 8 + j;
            float v = acc[i][j] * scale;
            if (EPI == 1) v += bias[n];
            if (EPI == 2) v += bias[m] + resid[(size_t)bz * sR + (size_t)m * Nn + n];
            C[(size_t)m * Nn + n] = v;
        }
    }
}

// ---------------------------------------------------------------
extern "C" void kernel_launch(void* const* d_in, const int* in_sizes, int n_in,
                              void* d_out, int out_size)
{
    const float* x    = (const float*)d_in[0];
    const float* gn_w = (const float*)d_in[1];
    const float* gn_b = (const float*)d_in[2];
    const float* wq   = (const float*)d_in[3];
    const float* bq   = (const float*)d_in[4];
    const float* wk   = (const float*)d_in[5];
    const float* bk   = (const float*)d_in[6];
    const float* wv   = (const float*)d_in[7];
    const float* bv   = (const float*)d_in[8];
    const float* wo   = (const float*)d_in[9];
    const float* bo   = (const float*)d_in[10];
    float* out = (float*)d_out;

    float *hn, *q, *k, *v, *o, *s;
    cudaGetSymbolAddress((void**)&hn, g_hn);
    cudaGetSymbolAddress((void**)&q,  g_q);
    cudaGetSymbolAddress((void**)&k,  g_k);
    cudaGetSymbolAddress((void**)&v,  g_v);
    cudaGetSymbolAddress((void**)&o,  g_o);
    cudaGetSymbolAddress((void**)&s,  g_s);

    const size_t sTok = (size_t)NTOK * CCH;   // per-batch stride for [n,c] tensors
    const size_t sChn = (size_t)CCH * NTOK;   // per-batch stride for [c,n] tensors
    const size_t sAtt = (size_t)NTOK * NTOK;
    const float att_scale = 1.0f / sqrtf((float)CCH);

    // 1) GroupNorm -> g_hn  [b, c, n]
    groupnorm_kernel<<<BATCH * GRP, 256>>>(x, gn_w, gn_b);

    // 2) QKV projections: q[b,n,o] = sum_c hn[b,c,n] * wq[o,c] + bq[o]
    dim3 gqkv(CCH / 128, NTOK / 128, BATCH);
    gemm_kernel<1, 0, 1><<<gqkv, 256>>>(hn, wq, q, NTOK, CCH, CCH,
                                        sChn, 0, sTok, bq, nullptr, 0, 1.0f);
    gemm_kernel<1, 0, 1><<<gqkv, 256>>>(hn, wk, k, NTOK, CCH, CCH,
                                        sChn, 0, sTok, bk, nullptr, 0, 1.0f);
    gemm_kernel<1, 0, 1><<<gqkv, 256>>>(hn, wv, v, NTOK, CCH, CCH,
                                        sChn, 0, sTok, bv, nullptr, 0, 1.0f);

    // 3) S = scale * Q K^T   [b, n, n]
    dim3 gs(NTOK / 128, NTOK / 128, BATCH);
    gemm_kernel<0, 0, 0><<<gs, 256>>>(q, k, s, NTOK, NTOK, CCH,
                                      sTok, sTok, sAtt, nullptr, nullptr, 0, att_scale);

    // 4) row softmax over S
    softmax_kernel<<<BATCH * NTOK, 256>>>();

    // 5) O = P V   [b, n, c]
    dim3 go(CCH / 128, NTOK / 128, BATCH);
    gemm_kernel<0, 1, 0><<<go, 256>>>(s, v, o, NTOK, CCH, NTOK,
                                      sAtt, sTok, sTok, nullptr, nullptr, 0, 1.0f);

    // 6) out[b,c,n] = x + bo[c] + sum_k wo[c,k] * O[b,n,k]
    dim3 gp(NTOK / 128, CCH / 128, BATCH);
    gemm_kernel<0, 0, 2><<<gp, 256>>>(wo, o, out, CCH, NTOK, CCH,
                                      0, sTok, sChn, bo, x, sChn, 1.0f);
}

// round 2
// speedup vs baseline: 2.2423x; 2.2423x over previous
#include <cuda_runtime.h>
#include <math.h>
#include <stdint.h>

#define BATCH 2
#define CCH   512
#define NTOK  4096
#define GRP   32
#define CPG   (CCH / GRP)
#define EPSV  1e-6f

#define BM 128
#define BN 128
#define BK 32
#define SSTR 136   // smem row stride in floats (bank = 8k+g permutation)

// -------- scratch (no allocation allowed; __device__ globals) --------
__device__ float g_hn[(size_t)BATCH * CCH * NTOK];          // groupnorm output  [b, c, n]
__device__ float g_q [(size_t)BATCH * NTOK * CCH];          // [b, n, c]
__device__ float g_k [(size_t)BATCH * NTOK * CCH];
__device__ float g_v [(size_t)BATCH * NTOK * CCH];
__device__ float g_o [(size_t)BATCH * NTOK * CCH];
__device__ float g_s [(size_t)BATCH * NTOK * NTOK];         // attention scores / probs

// ---------------------------------------------------------------
__device__ __forceinline__ uint32_t f2tf32(float f) {
    uint32_t u;
    asm("cvt.rna.tf32.f32 %0, %1;" : "=r"(u) : "f"(f));
    return u;
}

__device__ __forceinline__ void mma_tf32(float* d, const uint32_t* a, const uint32_t* b) {
    asm volatile(
        "mma.sync.aligned.m16n8k8.row.col.f32.tf32.tf32.f32 "
        "{%0,%1,%2,%3},{%4,%5,%6,%7},{%8,%9},{%0,%1,%2,%3};"
        : "+f"(d[0]), "+f"(d[1]), "+f"(d[2]), "+f"(d[3])
        : "r"(a[0]), "r"(a[1]), "r"(a[2]), "r"(a[3]), "r"(b[0]), "r"(b[1]));
}

// ---------------------------------------------------------------
// GroupNorm: one block per (batch, group)
// ---------------------------------------------------------------
__global__ void groupnorm_kernel(const float* __restrict__ x,
                                 const float* __restrict__ w,
                                 const float* __restrict__ b)
{
    const int bg = blockIdx.x;
    const int bb = bg / GRP;
    const int g  = bg % GRP;
    const int NE = CPG * NTOK;
    const size_t base = ((size_t)bb * CCH + (size_t)g * CPG) * NTOK;

    float s = 0.f, ss = 0.f;
    for (int i = threadIdx.x; i < NE; i += blockDim.x) {
        float v = x[base + i];
        s += v; ss += v * v;
    }
    __shared__ float sh[256], sh2[256];
    sh[threadIdx.x] = s; sh2[threadIdx.x] = ss;
    __syncthreads();
    for (int o = 128; o > 0; o >>= 1) {
        if (threadIdx.x < o) {
            sh[threadIdx.x]  += sh[threadIdx.x + o];
            sh2[threadIdx.x] += sh2[threadIdx.x + o];
        }
        __syncthreads();
    }
    const float mu   = sh[0] / (float)NE;
    const float var  = sh2[0] / (float)NE - mu * mu;
    const float rstd = rsqrtf(var + EPSV);

    for (int i = threadIdx.x; i < NE; i += blockDim.x) {
        int c = g * CPG + i / NTOK;
        float v = x[base + i];
        g_hn[base + i] = (v - mu) * rstd * w[c] + b[c];
    }
}

// ---------------------------------------------------------------
// Row softmax over g_s: one block per row (4096 elems, 16/thread)
// ---------------------------------------------------------------
__global__ void softmax_kernel()
{
    const size_t row = blockIdx.x;
    float* p = g_s + row * (size_t)NTOK;
    const int t = threadIdx.x;

    float loc[16];
    float mx = -1e30f;
#pragma unroll
    for (int i = 0; i < 16; i++) {
        loc[i] = p[t + i * 256];
        mx = fmaxf(mx, loc[i]);
    }
    __shared__ float sh[256];
    sh[t] = mx; __syncthreads();
    for (int o = 128; o > 0; o >>= 1) {
        if (t < o) sh[t] = fmaxf(sh[t], sh[t + o]);
        __syncthreads();
    }
    mx = sh[0];
    __syncthreads();

    float sum = 0.f;
#pragma unroll
    for (int i = 0; i < 16; i++) {
        loc[i] = __expf(loc[i] - mx);
        sum += loc[i];
    }
    sh[t] = sum; __syncthreads();
    for (int o = 128; o > 0; o >>= 1) {
        if (t < o) sh[t] += sh[t + o];
        __syncthreads();
    }
    const float inv = 1.0f / sh[0];
#pragma unroll
    for (int i = 0; i < 16; i++)
        p[t + i * 256] = loc[i] * inv;
}

// ---------------------------------------------------------------
// TF32 tensor-core GEMM: 128x128x32 CTA tile, 8 warps (2m x 4n),
// each warp 64x32 via 4x4 m16n8k8 mma. fp32 accumulate.
//   out[m*Nn+n] = scale * sum_k A(m,k)*B(n/k layout)  (+ epilogue)
// AL=0: A[m*K+k]   AL=1: A[k*M+m]
// BL=0: B[n*K+k]   BL=1: B[k*Nn+n]
// EPI=0: none  EPI=1: +bias[n]  EPI=2: +bias[m]+resid
// Dims assumed multiples of tile sizes (true here).
// ---------------------------------------------------------------
template<int AL, int BL, int EPI>
__global__ void __launch_bounds__(256, 2)
tc_gemm(const float* __restrict__ A,
        const float* __restrict__ B,
        float* __restrict__ C,
        int M, int Nn, int K,
        size_t sA, size_t sB, size_t sC,
        const float* __restrict__ bias,
        const float* __restrict__ resid, size_t sR,
        float scale)
{
    __shared__ __align__(16) uint32_t As[BK * SSTR];
    __shared__ __align__(16) uint32_t Bs[BK * SSTR];

    const int bn = blockIdx.x, bm = blockIdx.y, bz = blockIdx.z;
    A += (size_t)bz * sA;
    B += (size_t)bz * sB;
    C += (size_t)bz * sC;

    const int m0 = bm * BM, n0 = bn * BN;
    const int tid  = threadIdx.x;
    const int wid  = tid >> 5, lane = tid & 31;
    const int wm   = (wid & 1) * 64;
    const int wn   = (wid >> 1) * 32;
    const int g    = lane >> 2, tg = lane & 3;

    float acc[4][4][4] = {};

    for (int k0 = 0; k0 < K; k0 += BK) {
        // ---- stage A tile into As[k][m] (tf32 bits) ----
        if (AL == 0) {
            const int lrow = tid >> 1;
            const int lk   = (tid & 1) * 16;
            const float* ap = A + (size_t)(m0 + lrow) * K + k0 + lk;
#pragma unroll
            for (int i = 0; i < 4; i++) {
                float4 v = *reinterpret_cast<const float4*>(ap + 4 * i);
                As[(lk + 4 * i + 0) * SSTR + lrow] = f2tf32(v.x);
                As[(lk + 4 * i + 1) * SSTR + lrow] = f2tf32(v.y);
                As[(lk + 4 * i + 2) * SSTR + lrow] = f2tf32(v.z);
                As[(lk + 4 * i + 3) * SSTR + lrow] = f2tf32(v.w);
            }
        } else {
            const int lkr = tid >> 3;
            const int lm  = (tid & 7) * 16;
            const float* ap = A + (size_t)(k0 + lkr) * M + m0 + lm;
            uint32_t* dst = &As[lkr * SSTR + lm];
#pragma unroll
            for (int i = 0; i < 4; i++) {
                float4 v = *reinterpret_cast<const float4*>(ap + 4 * i);
                uint4 u = {f2tf32(v.x), f2tf32(v.y), f2tf32(v.z), f2tf32(v.w)};
                *reinterpret_cast<uint4*>(dst + 4 * i) = u;
            }
        }
        // ---- stage B tile into Bs[k][n] ----
        if (BL == 0) {
            const int lrow = tid >> 1;
            const int lk   = (tid & 1) * 16;
            const float* bp = B + (size_t)(n0 + lrow) * K + k0 + lk;
#pragma unroll
            for (int i = 0; i < 4; i++) {
                float4 v = *reinterpret_cast<const float4*>(bp + 4 * i);
                Bs[(lk + 4 * i + 0) * SSTR + lrow] = f2tf32(v.x);
                Bs[(lk + 4 * i + 1) * SSTR + lrow] = f2tf32(v.y);
                Bs[(lk + 4 * i + 2) * SSTR + lrow] = f2tf32(v.z);
                Bs[(lk + 4 * i + 3) * SSTR + lrow] = f2tf32(v.w);
            }
        } else {
            const int lkr = tid >> 3;
            const int ln  = (tid & 7) * 16;
            const float* bp = B + (size_t)(k0 + lkr) * Nn + n0 + ln;
            uint32_t* dst = &Bs[lkr * SSTR + ln];
#pragma unroll
            for (int i = 0; i < 4; i++) {
                float4 v = *reinterpret_cast<const float4*>(bp + 4 * i);
                uint4 u = {f2tf32(v.x), f2tf32(v.y), f2tf32(v.z), f2tf32(v.w)};
                *reinterpret_cast<uint4*>(dst + 4 * i) = u;
            }
        }
        __syncthreads();

#pragma unroll
        for (int ks = 0; ks < 4; ks++) {
            const int kk = ks * 8;
            uint32_t bf[4][2];
#pragma unroll
            for (int j = 0; j < 4; j++) {
                bf[j][0] = Bs[(kk + tg)     * SSTR + wn + 8 * j + g];
                bf[j][1] = Bs[(kk + tg + 4) * SSTR + wn + 8 * j + g];
            }
#pragma unroll
            for (int i = 0; i < 4; i++) {
                const int mrow = wm + 16 * i + g;
                uint32_t af[4];
                af[0] = As[(kk + tg)     * SSTR + mrow];
                af[1] = As[(kk + tg)     * SSTR + mrow + 8];
                af[2] = As[(kk + tg + 4) * SSTR + mrow];
                af[3] = As[(kk + tg + 4) * SSTR + mrow + 8];
#pragma unroll
                for (int j = 0; j < 4; j++)
                    mma_tf32(acc[i][j], af, bf[j]);
            }
        }
        __syncthreads();
    }

    // ---- epilogue ----
#pragma unroll
    for (int i = 0; i < 4; i++) {
        const int m = m0 + wm + 16 * i + g;
#pragma unroll
        for (int j = 0; j < 4; j++) {
            const int n = n0 + wn + 8 * j + 2 * tg;
            float v0 = acc[i][j][0] * scale;
            float v1 = acc[i][j][1] * scale;
            float v2 = acc[i][j][2] * scale;
            float v3 = acc[i][j][3] * scale;
            if (EPI == 1) { v0 += bias[n]; v1 += bias[n + 1]; v2 += bias[n]; v3 += bias[n + 1]; }
            if (EPI == 2) {
                const float* r0 = resid + (size_t)bz * sR + (size_t)m * Nn + n;
                const float* r1 = resid + (size_t)bz * sR + (size_t)(m + 8) * Nn + n;
                v0 += bias[m] + r0[0];
                v1 += bias[m] + r0[1];
                v2 += bias[m + 8] + r1[0];
                v3 += bias[m + 8] + r1[1];
            }
            *reinterpret_cast<float2*>(&C[(size_t)m * Nn + n])       = make_float2(v0, v1);
            *reinterpret_cast<float2*>(&C[(size_t)(m + 8) * Nn + n]) = make_float2(v2, v3);
        }
    }
}

// ---------------------------------------------------------------
extern "C" void kernel_launch(void* const* d_in, const int* in_sizes, int n_in,
                              void* d_out, int out_size)
{
    const float* x    = (const float*)d_in[0];
    const float* gn_w = (const float*)d_in[1];
    const float* gn_b = (const float*)d_in[2];
    const float* wq   = (const float*)d_in[3];
    const float* bq   = (const float*)d_in[4];
    const float* wk   = (const float*)d_in[5];
    const float* bk   = (const float*)d_in[6];
    const float* wv   = (const float*)d_in[7];
    const float* bv   = (const float*)d_in[8];
    const float* wo   = (const float*)d_in[9];
    const float* bo   = (const float*)d_in[10];
    float* out = (float*)d_out;

    float *hn, *q, *k, *v, *o, *s;
    cudaGetSymbolAddress((void**)&hn, g_hn);
    cudaGetSymbolAddress((void**)&q,  g_q);
    cudaGetSymbolAddress((void**)&k,  g_k);
    cudaGetSymbolAddress((void**)&v,  g_v);
    cudaGetSymbolAddress((void**)&o,  g_o);
    cudaGetSymbolAddress((void**)&s,  g_s);

    const size_t sTok = (size_t)NTOK * CCH;
    const size_t sChn = (size_t)CCH * NTOK;
    const size_t sAtt = (size_t)NTOK * NTOK;
    const float att_scale = 1.0f / sqrtf((float)CCH);

    // 1) GroupNorm -> g_hn  [b, c, n]
    groupnorm_kernel<<<BATCH * GRP, 256>>>(x, gn_w, gn_b);

    // 2) QKV: q[b,n,o] = sum_c hn[b,c,n] * wq[o,c] + bq[o]
    dim3 gqkv(CCH / BN, NTOK / BM, BATCH);
    tc_gemm<1, 0, 1><<<gqkv, 256>>>(hn, wq, q, NTOK, CCH, CCH,
                                    sChn, 0, sTok, bq, nullptr, 0, 1.0f);
    tc_gemm<1, 0, 1><<<gqkv, 256>>>(hn, wk, k, NTOK, CCH, CCH,
                                    sChn, 0, sTok, bk, nullptr, 0, 1.0f);
    tc_gemm<1, 0, 1><<<gqkv, 256>>>(hn, wv, v, NTOK, CCH, CCH,
                                    sChn, 0, sTok, bv, nullptr, 0, 1.0f);

    // 3) S = scale * Q K^T
    dim3 gs(NTOK / BN, NTOK / BM, BATCH);
    tc_gemm<0, 0, 0><<<gs, 256>>>(q, k, s, NTOK, NTOK, CCH,
                                  sTok, sTok, sAtt, nullptr, nullptr, 0, att_scale);

    // 4) row softmax
    softmax_kernel<<<BATCH * NTOK, 256>>>();

    // 5) O = P V
    dim3 go(CCH / BN, NTOK / BM, BATCH);
    tc_gemm<0, 1, 0><<<go, 256>>>(s, v, o, NTOK, CCH, NTOK,
                                  sAtt, sTok, sTok, nullptr, nullptr, 0, 1.0f);

    // 6) out[b,c,n] = x + bo[c] + sum_k wo[c,k] * O[b,n,k]
    dim3 gp(NTOK / BN, CCH / BM, BATCH);
    tc_gemm<0, 0, 2><<<gp, 256>>>(wo, o, out, CCH, NTOK, CCH,
                                  0, sTok, sChn, bo, x, sChn, 1.0f);
}

// round 3
// speedup vs baseline: 3.3083x; 1.4754x over previous
#include <cuda_runtime.h>
#include <math.h>
#include <stdint.h>

#define BATCH 2
#define CCH   512
#define NTOK  4096
#define GRP   32
#define CPG   (CCH / GRP)
#define EPSV  1e-6f

#define BM 128
#define BN 128
#define BK 16          // per pipeline stage
#define STRK 20        // smem row stride, K-contiguous layout [row][k]
#define STRM 136       // smem row stride, M-contiguous layout [k][m]
#define STAGE_F 2560   // floats per stage buffer (max of 128*20, 16*136)

// -------- scratch (no allocation allowed; __device__ globals) --------
__device__ float g_hn[(size_t)BATCH * CCH * NTOK];
__device__ float g_q [(size_t)BATCH * NTOK * CCH];
__device__ float g_k [(size_t)BATCH * NTOK * CCH];
__device__ float g_v [(size_t)BATCH * NTOK * CCH];
__device__ float g_o [(size_t)BATCH * NTOK * CCH];
__device__ float g_s [(size_t)BATCH * NTOK * NTOK];

// ---------------------------------------------------------------
__device__ __forceinline__ void cp16(float* dst, const float* src) {
    uint32_t d = (uint32_t)__cvta_generic_to_shared(dst);
    asm volatile("cp.async.cg.shared.global [%0], [%1], 16;" :: "r"(d), "l"(src));
}
#define CP_COMMIT() asm volatile("cp.async.commit_group;")
#define CP_WAIT1()  asm volatile("cp.async.wait_group 1;")

__device__ __forceinline__ void mma_tf32(float* d, const uint32_t* a, const uint32_t* b) {
    asm volatile(
        "mma.sync.aligned.m16n8k8.row.col.f32.tf32.tf32.f32 "
        "{%0,%1,%2,%3},{%4,%5,%6,%7},{%8,%9},{%0,%1,%2,%3};"
        : "+f"(d[0]), "+f"(d[1]), "+f"(d[2]), "+f"(d[3])
        : "r"(a[0]), "r"(a[1]), "r"(a[2]), "r"(a[3]), "r"(b[0]), "r"(b[1]));
}

// ---------------------------------------------------------------
// GroupNorm: one block per (batch, group)
// ---------------------------------------------------------------
__global__ void groupnorm_kernel(const float* __restrict__ x,
                                 const float* __restrict__ w,
                                 const float* __restrict__ b)
{
    const int bg = blockIdx.x;
    const int bb = bg / GRP;
    const int g  = bg % GRP;
    const int NE = CPG * NTOK;
    const size_t base = ((size_t)bb * CCH + (size_t)g * CPG) * NTOK;

    float s = 0.f, ss = 0.f;
    for (int i = threadIdx.x; i < NE; i += blockDim.x) {
        float v = x[base + i];
        s += v; ss += v * v;
    }
    __shared__ float sh[256], sh2[256];
    sh[threadIdx.x] = s; sh2[threadIdx.x] = ss;
    __syncthreads();
    for (int o = 128; o > 0; o >>= 1) {
        if (threadIdx.x < o) {
            sh[threadIdx.x]  += sh[threadIdx.x + o];
            sh2[threadIdx.x] += sh2[threadIdx.x + o];
        }
        __syncthreads();
    }
    const float mu   = sh[0] / (float)NE;
    const float var  = sh2[0] / (float)NE - mu * mu;
    const float rstd = rsqrtf(var + EPSV);

    for (int i = threadIdx.x; i < NE; i += blockDim.x) {
        int c = g * CPG + i / NTOK;
        float v = x[base + i];
        g_hn[base + i] = (v - mu) * rstd * w[c] + b[c];
    }
}

// ---------------------------------------------------------------
// Row softmax: one block per row
// ---------------------------------------------------------------
__global__ void softmax_kernel()
{
    const size_t row = blockIdx.x;
    float* p = g_s + row * (size_t)NTOK;
    const int t = threadIdx.x;

    float loc[16];
    float mx = -1e30f;
#pragma unroll
    for (int i = 0; i < 16; i++) {
        loc[i] = p[t + i * 256];
        mx = fmaxf(mx, loc[i]);
    }
    __shared__ float sh[256];
    sh[t] = mx; __syncthreads();
    for (int o = 128; o > 0; o >>= 1) {
        if (t < o) sh[t] = fmaxf(sh[t], sh[t + o]);
        __syncthreads();
    }
    mx = sh[0];
    __syncthreads();

    float sum = 0.f;
#pragma unroll
    for (int i = 0; i < 16; i++) {
        loc[i] = __expf(loc[i] - mx);
        sum += loc[i];
    }
    sh[t] = sum; __syncthreads();
    for (int o = 128; o > 0; o >>= 1) {
        if (t < o) sh[t] += sh[t + o];
        __syncthreads();
    }
    const float inv = 1.0f / sh[0];
#pragma unroll
    for (int i = 0; i < 16; i++)
        p[t + i * 256] = loc[i] * inv;
}

// ---------------------------------------------------------------
// Stage loaders (cp.async 16B). L=0: source is row-major [row][K]
// (K contiguous) -> smem [row][k] stride STRK. L=1: source is
// [k][M] (M contiguous) -> smem [k][m] stride STRM.
// ---------------------------------------------------------------
template<int L>
__device__ __forceinline__ void stage_load(float* s, const float* gbase,
                                           int ld, int k0, int r0, int tid)
{
    if (L == 0) {
#pragma unroll
        for (int r = 0; r < 2; r++) {
            int idx = tid + r * 256;
            int row = idx >> 2;
            int kc  = (idx & 3) * 4;
            cp16(&s[row * STRK + kc], gbase + (size_t)(r0 + row) * ld + k0 + kc);
        }
    } else {
#pragma unroll
        for (int r = 0; r < 2; r++) {
            int idx = tid + r * 256;
            int k  = idx >> 5;
            int mc = (idx & 31) * 4;
            cp16(&s[k * STRM + mc], gbase + (size_t)(k0 + k) * ld + r0 + mc);
        }
    }
}

template<int L>
__device__ __forceinline__ uint32_t ldfrag(const float* s, int row, int k)
{
    return __float_as_uint(L == 0 ? s[row * STRK + k] : s[k * STRM + row]);
}

// ---------------------------------------------------------------
// Core GEMM body: 128x128 CTA tile, BK=16 stages, 2-stage cp.async
// double buffer, 8 warps (2m x 4n), each 64x32 via 4x4 m16n8k8.
// A, B, C, resid already batch-offset.
// ---------------------------------------------------------------
template<int AL, int BL, int EPI>
__device__ __forceinline__ void gemm_body(
    float* As, float* Bs,                     // [2][STAGE_F] each
    const float* __restrict__ A, const float* __restrict__ B,
    float* __restrict__ C,
    int M, int Nn, int K, int m0, int n0,
    const float* __restrict__ bias,
    const float* __restrict__ resid, float scale)
{
    const int tid  = threadIdx.x;
    const int wid  = tid >> 5, lane = tid & 31;
    const int wm   = (wid & 1) * 64;
    const int wn   = (wid >> 1) * 32;
    const int g    = lane >> 2, tg = lane & 3;
    const int ldA_g = (AL == 0) ? K : M;
    const int ldB_g = (BL == 0) ? K : Nn;

    float acc[4][4][4] = {};

    const int KT = K / BK;

    stage_load<AL>(As, A, ldA_g, 0, m0, tid);
    stage_load<BL>(Bs, B, ldB_g, 0, n0, tid);
    CP_COMMIT();

    for (int kt = 0; kt < KT; kt++) {
        if (kt + 1 < KT) {
            float* an = As + ((kt + 1) & 1) * STAGE_F;
            float* bn = Bs + ((kt + 1) & 1) * STAGE_F;
            stage_load<AL>(an, A, ldA_g, (kt + 1) * BK, m0, tid);
            stage_load<BL>(bn, B, ldB_g, (kt + 1) * BK, n0, tid);
        }
        CP_COMMIT();
        CP_WAIT1();
        __syncthreads();

        const float* as = As + (kt & 1) * STAGE_F;
        const float* bs = Bs + (kt & 1) * STAGE_F;

#pragma unroll
        for (int ks = 0; ks < 2; ks++) {
            const int kk = ks * 8;
            uint32_t bf[4][2];
#pragma unroll
            for (int j = 0; j < 4; j++) {
                bf[j][0] = ldfrag<BL>(bs, wn + 8 * j + g, kk + tg);
                bf[j][1] = ldfrag<BL>(bs, wn + 8 * j + g, kk + tg + 4);
            }
#pragma unroll
            for (int i = 0; i < 4; i++) {
                const int mrow = wm + 16 * i + g;
                uint32_t af[4];
                af[0] = ldfrag<AL>(as, mrow,     kk + tg);
                af[1] = ldfrag<AL>(as, mrow + 8, kk + tg);
                af[2] = ldfrag<AL>(as, mrow,     kk + tg + 4);
                af[3] = ldfrag<AL>(as, mrow + 8, kk + tg + 4);
#pragma unroll
                for (int j = 0; j < 4; j++)
                    mma_tf32(acc[i][j], af, bf[j]);
            }
        }
        __syncthreads();
    }

    // ---- epilogue ----
#pragma unroll
    for (int i = 0; i < 4; i++) {
        const int m = m0 + wm + 16 * i + g;
#pragma unroll
        for (int j = 0; j < 4; j++) {
            const int n = n0 + wn + 8 * j + 2 * tg;
            float v0 = acc[i][j][0] * scale;
            float v1 = acc[i][j][1] * scale;
            float v2 = acc[i][j][2] * scale;
            float v3 = acc[i][j][3] * scale;
            if (EPI == 1) { v0 += bias[n]; v1 += bias[n + 1]; v2 += bias[n]; v3 += bias[n + 1]; }
            if (EPI == 2) {
                const float* r0 = resid + (size_t)m * Nn + n;
                const float* r1 = resid + (size_t)(m + 8) * Nn + n;
                v0 += bias[m] + r0[0];
                v1 += bias[m] + r0[1];
                v2 += bias[m + 8] + r1[0];
                v3 += bias[m + 8] + r1[1];
            }
            *reinterpret_cast<float2*>(&C[(size_t)m * Nn + n])       = make_float2(v0, v1);
            *reinterpret_cast<float2*>(&C[(size_t)(m + 8) * Nn + n]) = make_float2(v2, v3);
        }
    }
}

// ---------------------------------------------------------------
template<int AL, int BL, int EPI>
__global__ void __launch_bounds__(256, 2)
tc_gemm(const float* __restrict__ A, const float* __restrict__ B,
        float* __restrict__ C, int M, int Nn, int K,
        size_t sA, size_t sB, size_t sC,
        const float* __restrict__ bias,
        const float* __restrict__ resid, size_t sR, float scale)
{
    __shared__ __align__(16) float As[2][STAGE_F];
    __shared__ __align__(16) float Bs[2][STAGE_F];
    const int bz = blockIdx.z;
    gemm_body<AL, BL, EPI>(&As[0][0], &Bs[0][0],
                           A + (size_t)bz * sA, B + (size_t)bz * sB,
                           C + (size_t)bz * sC,
                           M, Nn, K, blockIdx.y * BM, blockIdx.x * BN,
                           bias, resid ? resid + (size_t)bz * sR : nullptr, scale);
}

// Fused QKV: grid.z = 3*BATCH; z = proj*BATCH + batch
__global__ void __launch_bounds__(256, 2)
qkv_gemm(const float* __restrict__ hn,
         const float* __restrict__ wq, const float* __restrict__ wk,
         const float* __restrict__ wv,
         const float* __restrict__ bq, const float* __restrict__ bk,
         const float* __restrict__ bv,
         float* __restrict__ q, float* __restrict__ k, float* __restrict__ v)
{
    __shared__ __align__(16) float As[2][STAGE_F];
    __shared__ __align__(16) float Bs[2][STAGE_F];
    const int p  = blockIdx.z / BATCH;
    const int bb = blockIdx.z % BATCH;
    const float* W  = (p == 0) ? wq : (p == 1) ? wk : wv;
    const float* bi = (p == 0) ? bq : (p == 1) ? bk : bv;
    float* out      = (p == 0) ? q  : (p == 1) ? k  : v;
    const size_t sChn = (size_t)CCH * NTOK;
    const size_t sTok = (size_t)NTOK * CCH;
    // out[n, o] = sum_c hn[c, n] * W[o, c] + bi[o]   (A layout: [k][M], AL=1)
    gemm_body<1, 0, 1>(&As[0][0], &Bs[0][0],
                       hn + (size_t)bb * sChn, W, out + (size_t)bb * sTok,
                       NTOK, CCH, CCH, blockIdx.y * BM, blockIdx.x * BN,
                       bi, nullptr, 1.0f);
}

// ---------------------------------------------------------------
extern "C" void kernel_launch(void* const* d_in, const int* in_sizes, int n_in,
                              void* d_out, int out_size)
{
    const float* x    = (const float*)d_in[0];
    const float* gn_w = (const float*)d_in[1];
    const float* gn_b = (const float*)d_in[2];
    const float* wq   = (const float*)d_in[3];
    const float* bq   = (const float*)d_in[4];
    const float* wk   = (const float*)d_in[5];
    const float* bk   = (const float*)d_in[6];
    const float* wv   = (const float*)d_in[7];
    const float* bv   = (const float*)d_in[8];
    const float* wo   = (const float*)d_in[9];
    const float* bo   = (const float*)d_in[10];
    float* out = (float*)d_out;

    float *hn, *q, *k, *v, *o, *s;
    cudaGetSymbolAddress((void**)&hn, g_hn);
    cudaGetSymbolAddress((void**)&q,  g_q);
    cudaGetSymbolAddress((void**)&k,  g_k);
    cudaGetSymbolAddress((void**)&v,  g_v);
    cudaGetSymbolAddress((void**)&o,  g_o);
    cudaGetSymbolAddress((void**)&s,  g_s);

    const size_t sTok = (size_t)NTOK * CCH;
    const size_t sChn = (size_t)CCH * NTOK;
    const size_t sAtt = (size_t)NTOK * NTOK;
    const float att_scale = 1.0f / sqrtf((float)CCH);

    // 1) GroupNorm -> g_hn [b, c, n]
    groupnorm_kernel<<<BATCH * GRP, 256>>>(x, gn_w, gn_b);

    // 2) fused QKV
    dim3 gqkv(CCH / BN, NTOK / BM, 3 * BATCH);
    qkv_gemm<<<gqkv, 256>>>(hn, wq, wk, wv, bq, bk, bv, q, k, v);

    // 3) S = scale * Q K^T
    dim3 gs(NTOK / BN, NTOK / BM, BATCH);
    tc_gemm<0, 0, 0><<<gs, 256>>>(q, k, s, NTOK, NTOK, CCH,
                                  sTok, sTok, sAtt, nullptr, nullptr, 0, att_scale);

    // 4) row softmax
    softmax_kernel<<<BATCH * NTOK, 256>>>();

    // 5) O = P V
    dim3 go(CCH / BN, NTOK / BM, BATCH);
    tc_gemm<0, 1, 0><<<go, 256>>>(s, v, o, NTOK, CCH, NTOK,
                                  sAtt, sTok, sTok, nullptr, nullptr, 0, 1.0f);

    // 6) out[b,c,n] = x + bo[c] + sum_k wo[c,k] * O[b,n,k]
    dim3 gp(NTOK / BN, CCH / BM, BATCH);
    tc_gemm<0, 0, 2><<<gp, 256>>>(wo, o, out, CCH, NTOK, CCH,
                                  0, sTok, sChn, bo, x, sChn, 1.0f);
}

// round 4
// speedup vs baseline: 3.5931x; 1.0861x over previous
#include <cuda_runtime.h>
#include <math.h>
#include <stdint.h>

#define BATCH 2
#define CCH   512
#define NTOK  4096
#define GRP   32
#define CPG   (CCH / GRP)
#define EPSV  1e-6f

#define BM 128
#define BN 128
#define BK 16          // per pipeline stage
#define NSTG 3         // cp.async ring depth
#define STRK 20        // smem row stride, K-contiguous layout [row][k]
#define STRM 136       // smem row stride, M-contiguous layout [k][m]
#define STAGE_F 2560   // floats per stage buffer (max of 128*20, 16*136)

// -------- scratch (no allocation allowed; __device__ globals) --------
__device__ float g_hn[(size_t)BATCH * CCH * NTOK];
__device__ float g_q [(size_t)BATCH * NTOK * CCH];
__device__ float g_k [(size_t)BATCH * NTOK * CCH];
__device__ float g_v [(size_t)BATCH * NTOK * CCH];
__device__ float g_o [(size_t)BATCH * NTOK * CCH];
__device__ float g_s [(size_t)BATCH * NTOK * NTOK];

// ---------------------------------------------------------------
__device__ __forceinline__ void cp16(float* dst, const float* src) {
    uint32_t d = (uint32_t)__cvta_generic_to_shared(dst);
    asm volatile("cp.async.cg.shared.global [%0], [%1], 16;" :: "r"(d), "l"(src));
}
#define CP_COMMIT() asm volatile("cp.async.commit_group;")
#define CP_WAIT1()  asm volatile("cp.async.wait_group 1;")

__device__ __forceinline__ void mma_tf32(float* d, const uint32_t* a, const uint32_t* b) {
    asm volatile(
        "mma.sync.aligned.m16n8k8.row.col.f32.tf32.tf32.f32 "
        "{%0,%1,%2,%3},{%4,%5,%6,%7},{%8,%9},{%0,%1,%2,%3};"
        : "+f"(d[0]), "+f"(d[1]), "+f"(d[2]), "+f"(d[3])
        : "r"(a[0]), "r"(a[1]), "r"(a[2]), "r"(a[3]), "r"(b[0]), "r"(b[1]));
}

// ---------------------------------------------------------------
// GroupNorm: one block (1024 thr) per (batch, group)
// ---------------------------------------------------------------
__global__ void groupnorm_kernel(const float* __restrict__ x,
                                 const float* __restrict__ w,
                                 const float* __restrict__ b)
{
    const int bg = blockIdx.x;
    const int bb = bg / GRP;
    const int g  = bg % GRP;
    const int NE = CPG * NTOK;
    const size_t base = ((size_t)bb * CCH + (size_t)g * CPG) * NTOK;
    const int t = threadIdx.x;

    float s = 0.f, ss = 0.f;
    for (int i = t * 4; i < NE; i += blockDim.x * 4) {
        float4 v = *reinterpret_cast<const float4*>(&x[base + i]);
        s  += v.x + v.y + v.z + v.w;
        ss += v.x * v.x + v.y * v.y + v.z * v.z + v.w * v.w;
    }
    __shared__ float sh[1024], sh2[1024];
    sh[t] = s; sh2[t] = ss;
    __syncthreads();
    for (int o = 512; o > 0; o >>= 1) {
        if (t < o) { sh[t] += sh[t + o]; sh2[t] += sh2[t + o]; }
        __syncthreads();
    }
    const float mu   = sh[0] / (float)NE;
    const float var  = sh2[0] / (float)NE - mu * mu;
    const float rstd = rsqrtf(var + EPSV);

    for (int i = t * 4; i < NE; i += blockDim.x * 4) {
        int c = g * CPG + i / NTOK;       // 4 elems share a channel (NTOK%4==0)
        float sc = rstd * w[c];
        float sb = b[c] - mu * sc;
        float4 v = *reinterpret_cast<const float4*>(&x[base + i]);
        v.x = v.x * sc + sb; v.y = v.y * sc + sb;
        v.z = v.z * sc + sb; v.w = v.w * sc + sb;
        *reinterpret_cast<float4*>(&g_hn[base + i]) = v;
    }
}

// ---------------------------------------------------------------
// Row softmax: one block per row
// ---------------------------------------------------------------
__global__ void softmax_kernel()
{
    const size_t row = blockIdx.x;
    float* p = g_s + row * (size_t)NTOK;
    const int t = threadIdx.x;

    float loc[16];
    float mx = -1e30f;
#pragma unroll
    for (int i = 0; i < 4; i++) {
        float4 v = *reinterpret_cast<const float4*>(&p[t * 4 + i * 1024]);
        loc[4*i] = v.x; loc[4*i+1] = v.y; loc[4*i+2] = v.z; loc[4*i+3] = v.w;
        mx = fmaxf(mx, fmaxf(fmaxf(v.x, v.y), fmaxf(v.z, v.w)));
    }
    __shared__ float sh[256];
    sh[t] = mx; __syncthreads();
    for (int o = 128; o > 0; o >>= 1) {
        if (t < o) sh[t] = fmaxf(sh[t], sh[t + o]);
        __syncthreads();
    }
    mx = sh[0];
    __syncthreads();

    float sum = 0.f;
#pragma unroll
    for (int i = 0; i < 16; i++) {
        loc[i] = __expf(loc[i] - mx);
        sum += loc[i];
    }
    sh[t] = sum; __syncthreads();
    for (int o = 128; o > 0; o >>= 1) {
        if (t < o) sh[t] += sh[t + o];
        __syncthreads();
    }
    const float inv = 1.0f / sh[0];
#pragma unroll
    for (int i = 0; i < 4; i++) {
        float4 v = make_float4(loc[4*i] * inv, loc[4*i+1] * inv,
                               loc[4*i+2] * inv, loc[4*i+3] * inv);
        *reinterpret_cast<float4*>(&p[t * 4 + i * 1024]) = v;
    }
}

// ---------------------------------------------------------------
// Stage loaders (cp.async 16B). L=0: source row-major [row][K]
// -> smem [row][k] stride STRK. L=1: source [k][M] -> smem [k][m]
// stride STRM.
// ---------------------------------------------------------------
template<int L>
__device__ __forceinline__ void stage_load(float* s, const float* gbase,
                                           int ld, int k0, int r0, int tid)
{
    if (L == 0) {
#pragma unroll
        for (int r = 0; r < 2; r++) {
            int idx = tid + r * 256;
            int row = idx >> 2;
            int kc  = (idx & 3) * 4;
            cp16(&s[row * STRK + kc], gbase + (size_t)(r0 + row) * ld + k0 + kc);
        }
    } else {
#pragma unroll
        for (int r = 0; r < 2; r++) {
            int idx = tid + r * 256;
            int k  = idx >> 5;
            int mc = (idx & 31) * 4;
            cp16(&s[k * STRM + mc], gbase + (size_t)(k0 + k) * ld + r0 + mc);
        }
    }
}

template<int L>
__device__ __forceinline__ uint32_t ldfrag(const float* s, int row, int k)
{
    return __float_as_uint(L == 0 ? s[row * STRK + k] : s[k * STRM + row]);
}

// ---------------------------------------------------------------
// Core GEMM body: 128x128 CTA tile, BK=16, 3-buffer cp.async ring
// with prefetch distance 2 and ONE __syncthreads per k-tile.
// 8 warps (2m x 4n), each warp 64x32 via 4x4 m16n8k8 tf32 mma.
// ---------------------------------------------------------------
template<int AL, int BL, int EPI>
__device__ __forceinline__ void gemm_body(
    float* As, float* Bs,                     // [NSTG][STAGE_F] each
    const float* __restrict__ A, const float* __restrict__ B,
    float* __restrict__ C,
    int M, int Nn, int K, int m0, int n0,
    const float* __restrict__ bias,
    const float* __restrict__ resid, float scale)
{
    const int tid  = threadIdx.x;
    const int wid  = tid >> 5, lane = tid & 31;
    const int wm   = (wid & 1) * 64;
    const int wn   = (wid >> 1) * 32;
    const int g    = lane >> 2, tg = lane & 3;
    const int ldA_g = (AL == 0) ? K : M;
    const int ldB_g = (BL == 0) ? K : Nn;

    float acc[4][4][4] = {};
    const int KT = K / BK;

    // prologue: prefetch tiles 0 and 1
    stage_load<AL>(As + 0 * STAGE_F, A, ldA_g, 0, m0, tid);
    stage_load<BL>(Bs + 0 * STAGE_F, B, ldB_g, 0, n0, tid);
    CP_COMMIT();
    stage_load<AL>(As + 1 * STAGE_F, A, ldA_g, BK, m0, tid);
    stage_load<BL>(Bs + 1 * STAGE_F, B, ldB_g, BK, n0, tid);
    CP_COMMIT();

    for (int kt = 0; kt < KT; kt++) {
        CP_WAIT1();               // group kt complete (<=1 outstanding)
        __syncthreads();          // also: everyone done reading buf[(kt+2)%3]

        if (kt + 2 < KT) {
            const int sb = (kt + 2) % NSTG;
            stage_load<AL>(As + sb * STAGE_F, A, ldA_g, (kt + 2) * BK, m0, tid);
            stage_load<BL>(Bs + sb * STAGE_F, B, ldB_g, (kt + 2) * BK, n0, tid);
        }
        CP_COMMIT();              // unconditional: keeps group accounting uniform

        const float* as = As + (kt % NSTG) * STAGE_F;
        const float* bs = Bs + (kt % NSTG) * STAGE_F;

#pragma unroll
        for (int ks = 0; ks < 2; ks++) {
            const int kk = ks * 8;
            uint32_t bf[4][2];
#pragma unroll
            for (int j = 0; j < 4; j++) {
                bf[j][0] = ldfrag<BL>(bs, wn + 8 * j + g, kk + tg);
                bf[j][1] = ldfrag<BL>(bs, wn + 8 * j + g, kk + tg + 4);
            }
#pragma unroll
            for (int i = 0; i < 4; i++) {
                const int mrow = wm + 16 * i + g;
                uint32_t af[4];
                af[0] = ldfrag<AL>(as, mrow,     kk + tg);
                af[1] = ldfrag<AL>(as, mrow + 8, kk + tg);
                af[2] = ldfrag<AL>(as, mrow,     kk + tg + 4);
                af[3] = ldfrag<AL>(as, mrow + 8, kk + tg + 4);
#pragma unroll
                for (int j = 0; j < 4; j++)
                    mma_tf32(acc[i][j], af, bf[j]);
            }
        }
    }

    // ---- epilogue ----
#pragma unroll
    for (int i = 0; i < 4; i++) {
        const int m = m0 + wm + 16 * i + g;
#pragma unroll
        for (int j = 0; j < 4; j++) {
            const int n = n0 + wn + 8 * j + 2 * tg;
            float v0 = acc[i][j][0] * scale;
            float v1 = acc[i][j][1] * scale;
            float v2 = acc[i][j][2] * scale;
            float v3 = acc[i][j][3] * scale;
            if (EPI == 1) { v0 += bias[n]; v1 += bias[n + 1]; v2 += bias[n]; v3 += bias[n + 1]; }
            if (EPI == 2) {
                const float* r0 = resid + (size_t)m * Nn + n;
                const float* r1 = resid + (size_t)(m + 8) * Nn + n;
                v0 += bias[m] + r0[0];
                v1 += bias[m] + r0[1];
                v2 += bias[m + 8] + r1[0];
                v3 += bias[m + 8] + r1[1];
            }
            *reinterpret_cast<float2*>(&C[(size_t)m * Nn + n])       = make_float2(v0, v1);
            *reinterpret_cast<float2*>(&C[(size_t)(m + 8) * Nn + n]) = make_float2(v2, v3);
        }
    }
}

// ---------------------------------------------------------------
template<int AL, int BL, int EPI>
__global__ void __launch_bounds__(256, 2)
tc_gemm(const float* __restrict__ A, const float* __restrict__ B,
        float* __restrict__ C, int M, int Nn, int K,
        size_t sA, size_t sB, size_t sC,
        const float* __restrict__ bias,
        const float* __restrict__ resid, size_t sR, float scale)
{
    __shared__ __align__(16) float As[NSTG][STAGE_F];
    __shared__ __align__(16) float Bs[NSTG][STAGE_F];
    const int bz = blockIdx.z;
    gemm_body<AL, BL, EPI>(&As[0][0], &Bs[0][0],
                           A + (size_t)bz * sA, B + (size_t)bz * sB,
                           C + (size_t)bz * sC,
                           M, Nn, K, blockIdx.y * BM, blockIdx.x * BN,
                           bias, resid ? resid + (size_t)bz * sR : nullptr, scale);
}

// Fused QKV: grid.z = 3*BATCH; z = proj*BATCH + batch
__global__ void __launch_bounds__(256, 2)
qkv_gemm(const float* __restrict__ hn,
         const float* __restrict__ wq, const float* __restrict__ wk,
         const float* __restrict__ wv,
         const float* __restrict__ bq, const float* __restrict__ bk,
         const float* __restrict__ bv,
         float* __restrict__ q, float* __restrict__ k, float* __restrict__ v)
{
    __shared__ __align__(16) float As[NSTG][STAGE_F];
    __shared__ __align__(16) float Bs[NSTG][STAGE_F];
    const int p  = blockIdx.z / BATCH;
    const int bb = blockIdx.z % BATCH;
    const float* W  = (p == 0) ? wq : (p == 1) ? wk : wv;
    const float* bi = (p == 0) ? bq : (p == 1) ? bk : bv;
    float* out      = (p == 0) ? q  : (p == 1) ? k  : v;
    const size_t sChn = (size_t)CCH * NTOK;
    const size_t sTok = (size_t)NTOK * CCH;
    gemm_body<1, 0, 1>(&As[0][0], &Bs[0][0],
                       hn + (size_t)bb * sChn, W, out + (size_t)bb * sTok,
                       NTOK, CCH, CCH, blockIdx.y * BM, blockIdx.x * BN,
                       bi, nullptr, 1.0f);
}

// ---------------------------------------------------------------
extern "C" void kernel_launch(void* const* d_in, const int* in_sizes, int n_in,
                              void* d_out, int out_size)
{
    const float* x    = (const float*)d_in[0];
    const float* gn_w = (const float*)d_in[1];
    const float* gn_b = (const float*)d_in[2];
    const float* wq   = (const float*)d_in[3];
    const float* bq   = (const float*)d_in[4];
    const float* wk   = (const float*)d_in[5];
    const float* bk   = (const float*)d_in[6];
    const float* wv   = (const float*)d_in[7];
    const float* bv   = (const float*)d_in[8];
    const float* wo   = (const float*)d_in[9];
    const float* bo   = (const float*)d_in[10];
    float* out = (float*)d_out;

    float *hn, *q, *k, *v, *o, *s;
    cudaGetSymbolAddress((void**)&hn, g_hn);
    cudaGetSymbolAddress((void**)&q,  g_q);
    cudaGetSymbolAddress((void**)&k,  g_k);
    cudaGetSymbolAddress((void**)&v,  g_v);
    cudaGetSymbolAddress((void**)&o,  g_o);
    cudaGetSymbolAddress((void**)&s,  g_s);

    const size_t sTok = (size_t)NTOK * CCH;
    const size_t sChn = (size_t)CCH * NTOK;
    const size_t sAtt = (size_t)NTOK * NTOK;
    const float att_scale = 1.0f / sqrtf((float)CCH);

    // 1) GroupNorm -> g_hn [b, c, n]
    groupnorm_kernel<<<BATCH * GRP, 1024>>>(x, gn_w, gn_b);

    // 2) fused QKV
    dim3 gqkv(CCH / BN, NTOK / BM, 3 * BATCH);
    qkv_gemm<<<gqkv, 256>>>(hn, wq, wk, wv, bq, bk, bv, q, k, v);

    // 3) S = scale * Q K^T
    dim3 gs(NTOK / BN, NTOK / BM, BATCH);
    tc_gemm<0, 0, 0><<<gs, 256>>>(q, k, s, NTOK, NTOK, CCH,
                                  sTok, sTok, sAtt, nullptr, nullptr, 0, att_scale);

    // 4) row softmax
    softmax_kernel<<<BATCH * NTOK, 256>>>();

    // 5) O = P V
    dim3 go(CCH / BN, NTOK / BM, BATCH);
    tc_gemm<0, 1, 0><<<go, 256>>>(s, v, o, NTOK, CCH, NTOK,
                                  sAtt, sTok, sTok, nullptr, nullptr, 0, 1.0f);

    // 6) out[b,c,n] = x + bo[c] + sum_k wo[c,k] * O[b,n,k]
    dim3 gp(NTOK / BN, CCH / BM, BATCH);
    tc_gemm<0, 0, 2><<<gp, 256>>>(wo, o, out, CCH, NTOK, CCH,
                                  0, sTok, sChn, bo, x, sChn, 1.0f);
}

// round 7
// speedup vs baseline: 7.7130x; 2.1466x over previous
#include <cuda_runtime.h>
#include <cuda_fp16.h>
#include <math.h>
#include <stdint.h>

#define BATCH 2
#define CCH   512
#define NTOK  4096
#define GRP   32
#define CPG   (CCH / GRP)
#define EPSV  1e-6f

// -------- scratch (__device__ globals; no allocation allowed) --------
__device__ __half g_hn[(size_t)BATCH * NTOK * CCH];   // GN out, TRANSPOSED [b, n, c]
__device__ __half g_q [(size_t)BATCH * NTOK * CCH];   // [b, n, c]
__device__ __half g_k [(size_t)BATCH * NTOK * CCH];   // [b, n, c]
__device__ __half g_vt[(size_t)BATCH * CCH * NTOK];   // V TRANSPOSED [b, c, n]
__device__ __half g_o [(size_t)BATCH * NTOK * CCH];   // [b, n, c]
__device__ float  g_s [(size_t)BATCH * NTOK * NTOK];  // raw scores (fp32)
__device__ __half g_p [(size_t)BATCH * NTOK * NTOK];  // softmax probs (fp16)
__device__ __half g_w16[4 * (size_t)CCH * CCH];       // wq, wk, wv, wo in fp16

// ---------------- helpers ----------------
__device__ __forceinline__ uint32_t smem_u32(const void* p) {
    uint32_t a;
    asm("{ .reg .u64 t; cvta.to.shared.u64 t, %1; cvt.u32.u64 %0, t; }"
        : "=r"(a) : "l"(p));
    return a;
}
__device__ __forceinline__ void cp16(void* dst, const void* src) {
    uint32_t d = smem_u32(dst);
    asm volatile("cp.async.cg.shared.global [%0], [%1], 16;" :: "r"(d), "l"(src));
}
#define CP_COMMIT() asm volatile("cp.async.commit_group;")

#define LDSM4(r0, r1, r2, r3, addr) \
    asm volatile("ldmatrix.sync.aligned.m8n8.x4.shared.b16 {%0,%1,%2,%3}, [%4];" \
        : "=r"(r0), "=r"(r1), "=r"(r2), "=r"(r3) : "r"(addr))

__device__ __forceinline__ void mma_f16(float* d, const uint32_t* a, const uint32_t* b) {
    asm volatile(
        "mma.sync.aligned.m16n8k16.row.col.f32.f16.f16.f32 "
        "{%0,%1,%2,%3},{%4,%5,%6,%7},{%8,%9},{%0,%1,%2,%3};"
        : "+f"(d[0]), "+f"(d[1]), "+f"(d[2]), "+f"(d[3])
        : "r"(a[0]), "r"(a[1]), "r"(a[2]), "r"(a[3]), "r"(b[0]), "r"(b[1]));
}

__device__ __forceinline__ uint32_t h2_bits(__half2 h) {
    uint32_t u;
    memcpy(&u, &h, 4);
    return u;
}

// ---------------------------------------------------------------
// Weight conversion fp32 -> fp16: grid (256, 4), block 256
// ---------------------------------------------------------------
__global__ void convw_kernel(const float* __restrict__ a, const float* __restrict__ b,
                             const float* __restrict__ c, const float* __restrict__ d)
{
    const float* srcs[4] = {a, b, c, d};
    const float* src = srcs[blockIdx.y];
    __half* dst = g_w16 + (size_t)blockIdx.y * CCH * CCH;
    int i = (blockIdx.x * 256 + threadIdx.x) * 4;
    float4 v = *reinterpret_cast<const float4*>(&src[i]);
    *reinterpret_cast<__half2*>(&dst[i])     = __floats2half2_rn(v.x, v.y);
    *reinterpret_cast<__half2*>(&dst[i + 2]) = __floats2half2_rn(v.z, v.w);
}

// ---------------------------------------------------------------
// GroupNorm + transpose: one block (1024 thr) per (batch, group).
// Reads x [b,c,n] fp32, writes g_hn TRANSPOSED [b,n,c] fp16.
// ---------------------------------------------------------------
__global__ void groupnorm_kernel(const float* __restrict__ x,
                                 const float* __restrict__ w,
                                 const float* __restrict__ b)
{
    const int bg = blockIdx.x;
    const int bb = bg / GRP;
    const int g  = bg % GRP;
    const int NE = CPG * NTOK;     // 65536
    const size_t base = ((size_t)bb * CCH + (size_t)g * CPG) * NTOK;
    const int t = threadIdx.x;

    float s = 0.f, ss = 0.f;
    for (int i = t * 4; i < NE; i += 4096) {
        float4 v = *reinterpret_cast<const float4*>(&x[base + i]);
        s  += v.x + v.y + v.z + v.w;
        ss += v.x * v.x + v.y * v.y + v.z * v.z + v.w * v.w;
    }
    __shared__ float sh[1024], sh2[1024];
    sh[t] = s; sh2[t] = ss;
    __syncthreads();
    for (int o = 512; o > 0; o >>= 1) {
        if (t < o) { sh[t] += sh[t + o]; sh2[t] += sh2[t + o]; }
        __syncthreads();
    }
    const float mu   = sh[0] / (float)NE;
    const float var  = sh2[0] / (float)NE - mu * mu;
    const float rstd = rsqrtf(var + EPSV);

    __shared__ float ts[16][65];
    const int c_l = t >> 6;          // 0..15 load role
    const int n_l = t & 63;
    const int c   = g * CPG + c_l;
    const float sc = rstd * w[c];
    const float sb = b[c] - mu * sc;
    const int wn = t >> 4;           // 0..63 store role
    const int wc = t & 15;
    __half* dst = g_hn + (size_t)bb * NTOK * CCH + g * CPG;

    for (int n0 = 0; n0 < NTOK; n0 += 64) {
        ts[c_l][n_l] = x[base + (size_t)c_l * NTOK + n0 + n_l] * sc + sb;
        __syncthreads();
        dst[(size_t)(n0 + wn) * CCH + wc] = __float2half_rn(ts[wc][wn]);
        __syncthreads();
    }
}

// ---------------------------------------------------------------
// Row softmax: reads g_s fp32, writes g_p fp16. One block per row.
// ---------------------------------------------------------------
__global__ void softmax_kernel()
{
    const size_t row = blockIdx.x;
    const float* p = g_s + row * (size_t)NTOK;
    __half* q = g_p + row * (size_t)NTOK;
    const int t = threadIdx.x;

    float loc[16];
    float mx = -1e30f;
#pragma unroll
    for (int i = 0; i < 4; i++) {
        float4 v = *reinterpret_cast<const float4*>(&p[t * 4 + i * 1024]);
        loc[4*i] = v.x; loc[4*i+1] = v.y; loc[4*i+2] = v.z; loc[4*i+3] = v.w;
        mx = fmaxf(mx, fmaxf(fmaxf(v.x, v.y), fmaxf(v.z, v.w)));
    }
    __shared__ float sh[256];
    sh[t] = mx; __syncthreads();
    for (int o = 128; o > 0; o >>= 1) {
        if (t < o) sh[t] = fmaxf(sh[t], sh[t + o]);
        __syncthreads();
    }
    mx = sh[0];
    __syncthreads();

    float sum = 0.f;
#pragma unroll
    for (int i = 0; i < 16; i++) {
        loc[i] = __expf(loc[i] - mx);
        sum += loc[i];
    }
    sh[t] = sum; __syncthreads();
    for (int o = 128; o > 0; o >>= 1) {
        if (t < o) sh[t] += sh[t + o];
        __syncthreads();
    }
    const float inv = 1.0f / sh[0];
#pragma unroll
    for (int i = 0; i < 4; i++) {
        __half2 h0 = __floats2half2_rn(loc[4*i] * inv,   loc[4*i+1] * inv);
        __half2 h1 = __floats2half2_rn(loc[4*i+2] * inv, loc[4*i+3] * inv);
        uint2 u = make_uint2(h2_bits(h0), h2_bits(h1));
        *reinterpret_cast<uint2*>(&q[t * 4 + i * 1024]) = u;
    }
}

// ---------------------------------------------------------------
// fp16 tensor-core GEMM:  C[m,n] = scale * sum_k A[m,k]*B[n,k] (+epi)
// A: [M,K] fp16 row-major.  B: [Nn,K] fp16 row-major. Tiles 128x128x64.
// 3-stage cp.async ring, 8 warps (2m x 4n), warp 64x32, m16n8k16+ldmatrix.
// EPI: 0 none | 1 +bias[n] | 2 +bias[m]+resid[m*Nn+n]
// OUTT: 0 fp32 | 1 fp16 | 2 fp16 transposed (C[n*M+m], for V^T)
// ---------------------------------------------------------------
template<int EPI, int OUTT>
__global__ void __launch_bounds__(256)
hgemm(const __half* __restrict__ A, const __half* __restrict__ B,
      void* __restrict__ Cv, int M, int Nn, int K,
      size_t sA, size_t sB, size_t sC,
      const float* __restrict__ bias,
      const float* __restrict__ resid, size_t sR, float scale)
{
    extern __shared__ __align__(1024) char smem[];   // 3 * (16KB A + 16KB B)
    const uint32_t sbase = smem_u32(smem);
    const int tid = threadIdx.x, wid = tid >> 5, lane = tid & 31;
    const int bz = blockIdx.z;
    A += (size_t)bz * sA;
    B += (size_t)bz * sB;
    const int m0 = blockIdx.y * 128, n0 = blockIdx.x * 128;
    const int wm = (wid & 1) * 64, wn = (wid >> 1) * 32;
    const int g = lane >> 2, tg = lane & 3;

    float acc[4][4][4] = {};

    auto stage = [&](int buf, int k0) {
        char* da = smem + buf * 32768;
        char* db = da + 16384;
#pragma unroll
        for (int i = 0; i < 4; i++) {
            int cid = tid + i * 256;
            int r = cid >> 3, c = cid & 7;
            uint32_t off = (uint32_t)(r * 128 + c * 16) ^ (uint32_t)((r & 7) << 4);
            cp16(da + off, A + (size_t)(m0 + r) * K + k0 + c * 8);
            cp16(db + off, B + (size_t)(n0 + r) * K + k0 + c * 8);
        }
    };

    // per-lane ldmatrix address pieces
    const int lrowA = lane & 15;          // A: row within 16
    const int coffA = lane >> 4;          // A: extra 16B chunk
    const int browB = ((lane >> 4) << 3) + (lane & 7);   // B: 0..15
    const int bcoB  = (lane >> 3) & 1;    // B: chunk parity
    const uint32_t swz = (uint32_t)((lane & 7) << 4);

    const int KT = K >> 6;
    stage(0, 0);  CP_COMMIT();
    stage(1, 64); CP_COMMIT();

    for (int kt = 0; kt < KT; kt++) {
        asm volatile("cp.async.wait_group 1;");
        __syncthreads();
        if (kt + 2 < KT) stage((kt + 2) % 3, (kt + 2) * 64);
        CP_COMMIT();

        const uint32_t abase = sbase + (kt % 3) * 32768;
        const uint32_t bbase = abase + 16384;

#pragma unroll
        for (int ks = 0; ks < 4; ks++) {
            uint32_t bf[4][2];
            {
                uint32_t addr = bbase + (uint32_t)((wn + browB) * 128)
                              + (((uint32_t)((ks * 2 + bcoB) * 16)) ^ swz);
                LDSM4(bf[0][0], bf[0][1], bf[1][0], bf[1][1], addr);
                LDSM4(bf[2][0], bf[2][1], bf[3][0], bf[3][1], addr + 16 * 128);
            }
#pragma unroll
            for (int i = 0; i < 4; i++) {
                uint32_t a[4];
                uint32_t addr = abase + (uint32_t)((wm + 16 * i + lrowA) * 128)
                              + (((uint32_t)((ks * 2 + coffA) * 16)) ^ swz);
                LDSM4(a[0], a[1], a[2], a[3], addr);
#pragma unroll
                for (int j = 0; j < 4; j++)
                    mma_f16(acc[i][j], a, bf[j]);
            }
        }
    }

    // ---------------- epilogue ----------------
    if (OUTT == 0) {
        float* C = (float*)Cv + (size_t)bz * sC;
        const float* rz = (EPI == 2) ? resid + (size_t)bz * sR : nullptr;
#pragma unroll
        for (int i = 0; i < 4; i++) {
            const int m = m0 + wm + 16 * i + g;
#pragma unroll
            for (int j = 0; j < 4; j++) {
                const int n = n0 + wn + 8 * j + 2 * tg;
                float v0 = acc[i][j][0] * scale, v1 = acc[i][j][1] * scale;
                float v2 = acc[i][j][2] * scale, v3 = acc[i][j][3] * scale;
                if (EPI == 1) { v0 += bias[n]; v1 += bias[n+1]; v2 += bias[n]; v3 += bias[n+1]; }
                if (EPI == 2) {
                    const float* r0 = rz + (size_t)m * Nn + n;
                    const float* r1 = rz + (size_t)(m + 8) * Nn + n;
                    v0 += bias[m] + r0[0];     v1 += bias[m] + r0[1];
                    v2 += bias[m + 8] + r1[0]; v3 += bias[m + 8] + r1[1];
                }
                *reinterpret_cast<float2*>(&C[(size_t)m * Nn + n])       = make_float2(v0, v1);
                *reinterpret_cast<float2*>(&C[(size_t)(m + 8) * Nn + n]) = make_float2(v2, v3);
            }
        }
    } else if (OUTT == 1) {
        __half* C = (__half*)Cv + (size_t)bz * sC;
#pragma unroll
        for (int i = 0; i < 4; i++) {
            const int m = m0 + wm + 16 * i + g;
#pragma unroll
            for (int j = 0; j < 4; j++) {
                const int n = n0 + wn + 8 * j + 2 * tg;
                float v0 = acc[i][j][0] * scale, v1 = acc[i][j][1] * scale;
                float v2 = acc[i][j][2] * scale, v3 = acc[i][j][3] * scale;
                if (EPI == 1) { v0 += bias[n]; v1 += bias[n+1]; v2 += bias[n]; v3 += bias[n+1]; }
                *reinterpret_cast<__half2*>(&C[(size_t)m * Nn + n])       = __floats2half2_rn(v0, v1);
                *reinterpret_cast<__half2*>(&C[(size_t)(m + 8) * Nn + n]) = __floats2half2_rn(v2, v3);
            }
        }
    } else {
        // transposed fp16 out: C[n * M + m]. Per-warp swizzled smem transpose.
        __half* C = (__half*)Cv + (size_t)bz * sC;
        __syncthreads();                       // done with stage buffers
        char* tp = smem + wid * 4096;          // 32 rows(n) x 128B(m)
#pragma unroll
        for (int i = 0; i < 4; i++) {
#pragma unroll
            for (int j = 0; j < 4; j++) {
                const int nl = 8 * j + 2 * tg;
                const int nch = n0 + wn + nl;
                float v0 = acc[i][j][0] * scale, v1 = acc[i][j][1] * scale;
                float v2 = acc[i][j][2] * scale, v3 = acc[i][j][3] * scale;
                if (EPI == 1) { v0 += bias[nch]; v1 += bias[nch+1]; v2 += bias[nch]; v3 += bias[nch+1]; }
                const int ml0 = 16 * i + g, ml1 = ml0 + 8;
                auto put = [&](int nn, int mm, float vv) {
                    uint32_t o = (uint32_t)(nn * 128 + ((((mm >> 3) ^ (nn & 7)) << 4)) + (mm & 7) * 2);
                    *reinterpret_cast<__half*>(tp + o) = __float2half_rn(vv);
                };
                put(nl,     ml0, v0); put(nl + 1, ml0, v1);
                put(nl,     ml1, v2); put(nl + 1, ml1, v3);
            }
        }
        __syncwarp();
#pragma unroll
        for (int r = 0; r < 32; r++) {
            uint32_t o = (uint32_t)(r * 128 + (((lane >> 2) ^ (r & 7)) << 4) + (lane & 3) * 4);
            uint32_t v = *reinterpret_cast<uint32_t*>(tp + o);
            *reinterpret_cast<uint32_t*>(&C[(size_t)(n0 + wn + r) * M + m0 + wm + lane * 2]) = v;
        }
    }
}

// ---------------------------------------------------------------
extern "C" void kernel_launch(void* const* d_in, const int* in_sizes, int n_in,
                              void* d_out, int out_size)
{
    const float* x    = (const float*)d_in[0];
    const float* gn_w = (const float*)d_in[1];
    const float* gn_b = (const float*)d_in[2];
    const float* wq   = (const float*)d_in[3];
    const float* bq   = (const float*)d_in[4];
    const float* wk   = (const float*)d_in[5];
    const float* bk   = (const float*)d_in[6];
    const float* wv   = (const float*)d_in[7];
    const float* bv   = (const float*)d_in[8];
    const float* wo   = (const float*)d_in[9];
    const float* bo   = (const float*)d_in[10];
    float* out = (float*)d_out;

    __half *hn, *q, *k, *vt, *o, *p, *w16;
    float* s;
    cudaGetSymbolAddress((void**)&hn, g_hn);
    cudaGetSymbolAddress((void**)&q,  g_q);
    cudaGetSymbolAddress((void**)&k,  g_k);
    cudaGetSymbolAddress((void**)&vt, g_vt);
    cudaGetSymbolAddress((void**)&o,  g_o);
    cudaGetSymbolAddress((void**)&s,  g_s);
    cudaGetSymbolAddress((void**)&p,  g_p);
    cudaGetSymbolAddress((void**)&w16, g_w16);
    const __half* wq16 = w16;
    const __half* wk16 = w16 + (size_t)CCH * CCH;
    const __half* wv16 = w16 + 2 * (size_t)CCH * CCH;
    const __half* wo16 = w16 + 3 * (size_t)CCH * CCH;

    const size_t sTok = (size_t)NTOK * CCH;
    const size_t sChn = (size_t)CCH * NTOK;
    const size_t sAtt = (size_t)NTOK * NTOK;
    const float att_scale = 1.0f / sqrtf((float)CCH);

    const int DS = 3 * 32768;   // 96 KB
    cudaFuncSetAttribute(hgemm<1, 1>, cudaFuncAttributeMaxDynamicSharedMemorySize, DS);
    cudaFuncSetAttribute(hgemm<1, 2>, cudaFuncAttributeMaxDynamicSharedMemorySize, DS);
    cudaFuncSetAttribute(hgemm<0, 0>, cudaFuncAttributeMaxDynamicSharedMemorySize, DS);
    cudaFuncSetAttribute(hgemm<0, 1>, cudaFuncAttributeMaxDynamicSharedMemorySize, DS);
    cudaFuncSetAttribute(hgemm<2, 0>, cudaFuncAttributeMaxDynamicSharedMemorySize, DS);

    // 0) convert weights to fp16
    convw_kernel<<<dim3(CCH * CCH / 1024, 4), 256>>>(wq, wk, wv, wo);

    // 1) GroupNorm -> g_hn [b, n, c] fp16 (transposed)
    groupnorm_kernel<<<BATCH * GRP, 1024>>>(x, gn_w, gn_b);

    // 2) Q, K (fp16 out), V (fp16 transposed out)
    dim3 gq(CCH / 128, NTOK / 128, BATCH);
    hgemm<1, 1><<<gq, 256, DS>>>(hn, wq16, q,  NTOK, CCH, CCH,
                                 sTok, 0, sTok, bq, nullptr, 0, 1.0f);
    hgemm<1, 1><<<gq, 256, DS>>>(hn, wk16, k,  NTOK, CCH, CCH,
                                 sTok, 0, sTok, bk, nullptr, 0, 1.0f);
    hgemm<1, 2><<<gq, 256, DS>>>(hn, wv16, vt, NTOK, CCH, CCH,
                                 sTok, 0, sChn, bv, nullptr, 0, 1.0f);

    // 3) S = scale * Q K^T  (fp32 out)
    dim3 gs(NTOK / 128, NTOK / 128, BATCH);
    hgemm<0, 0><<<gs, 256, DS>>>(q, k, s, NTOK, NTOK, CCH,
                                 sTok, sTok, sAtt, nullptr, nullptr, 0, att_scale);

    // 4) softmax -> g_p fp16
    softmax_kernel<<<BATCH * NTOK, 256>>>();

    // 5) O = P V  (A = P [n, j], B = V^T [c, j], fp16 out)
    dim3 gpv(CCH / 128, NTOK / 128, BATCH);
    hgemm<0, 1><<<gpv, 256, DS>>>(p, vt, o, NTOK, CCH, NTOK,
                                  sAtt, sChn, sTok, nullptr, nullptr, 0, 1.0f);

    // 6) out[b,c,n] = x + bo[c] + sum_k wo[c,k] * O[b,n,k]  (fp32 out)
    dim3 gp(NTOK / 128, CCH / 128, BATCH);
    hgemm<2, 0><<<gp, 256, DS>>>(wo16, o, out, CCH, NTOK, CCH,
                                 0, sTok, sChn, bo, x, sChn, 1.0f);
}

// round 8
// speedup vs baseline: 7.9519x; 1.0310x over previous
#include <cuda_runtime.h>
#include <cuda_fp16.h>
#include <math.h>
#include <stdint.h>

#define BATCH 2
#define CCH   512
#define NTOK  4096
#define GRP   32
#define CPG   (CCH / GRP)
#define EPSV  1e-6f

// GEMM tiling
#define BM 128
#define BN 256
#define BK 64
#define STAGE_BYTES (16384 + 32768)   // A 128x64 fp16 + B 256x64 fp16
#define DSMEM (3 * STAGE_BYTES)       // 147456

// -------- scratch (__device__ globals; no allocation allowed) --------
__device__ __half g_hn[(size_t)BATCH * NTOK * CCH];   // GN out, TRANSPOSED [b, n, c]
__device__ __half g_q [(size_t)BATCH * NTOK * CCH];   // [b, n, c]
__device__ __half g_k [(size_t)BATCH * NTOK * CCH];   // [b, n, c]
__device__ __half g_vt[(size_t)BATCH * CCH * NTOK];   // V TRANSPOSED [b, c, n]
__device__ __half g_o [(size_t)BATCH * NTOK * CCH];   // [b, n, c]
__device__ __half g_p [(size_t)BATCH * NTOK * NTOK];  // scores -> probs (fp16, in-place)
__device__ __half g_w16[4 * (size_t)CCH * CCH];       // wq, wk, wv, wo in fp16

// ---------------- helpers ----------------
__device__ __forceinline__ uint32_t smem_u32(const void* p) {
    uint32_t a;
    asm("{ .reg .u64 t; cvta.to.shared.u64 t, %1; cvt.u32.u64 %0, t; }"
        : "=r"(a) : "l"(p));
    return a;
}
__device__ __forceinline__ void cp16(void* dst, const void* src) {
    uint32_t d = smem_u32(dst);
    asm volatile("cp.async.cg.shared.global [%0], [%1], 16;" :: "r"(d), "l"(src));
}
#define CP_COMMIT() asm volatile("cp.async.commit_group;")

#define LDSM4(r0, r1, r2, r3, addr) \
    asm volatile("ldmatrix.sync.aligned.m8n8.x4.shared.b16 {%0,%1,%2,%3}, [%4];" \
        : "=r"(r0), "=r"(r1), "=r"(r2), "=r"(r3) : "r"(addr))

__device__ __forceinline__ void mma_f16(float* d, const uint32_t* a, const uint32_t* b) {
    asm volatile(
        "mma.sync.aligned.m16n8k16.row.col.f32.f16.f16.f32 "
        "{%0,%1,%2,%3},{%4,%5,%6,%7},{%8,%9},{%0,%1,%2,%3};"
        : "+f"(d[0]), "+f"(d[1]), "+f"(d[2]), "+f"(d[3])
        : "r"(a[0]), "r"(a[1]), "r"(a[2]), "r"(a[3]), "r"(b[0]), "r"(b[1]));
}

__device__ __forceinline__ uint32_t h2_bits(__half2 h) {
    uint32_t u;
    memcpy(&u, &h, 4);
    return u;
}

// ---------------------------------------------------------------
// Weight conversion fp32 -> fp16
// ---------------------------------------------------------------
__global__ void convw_kernel(const float* __restrict__ a, const float* __restrict__ b,
                             const float* __restrict__ c, const float* __restrict__ d)
{
    const float* srcs[4] = {a, b, c, d};
    const float* src = srcs[blockIdx.y];
    __half* dst = g_w16 + (size_t)blockIdx.y * CCH * CCH;
    int i = (blockIdx.x * 256 + threadIdx.x) * 4;
    float4 v = *reinterpret_cast<const float4*>(&src[i]);
    *reinterpret_cast<__half2*>(&dst[i])     = __floats2half2_rn(v.x, v.y);
    *reinterpret_cast<__half2*>(&dst[i + 2]) = __floats2half2_rn(v.z, v.w);
}

// ---------------------------------------------------------------
// GroupNorm + transpose: one block (1024 thr) per (batch, group).
// ---------------------------------------------------------------
__global__ void groupnorm_kernel(const float* __restrict__ x,
                                 const float* __restrict__ w,
                                 const float* __restrict__ b)
{
    const int bg = blockIdx.x;
    const int bb = bg / GRP;
    const int g  = bg % GRP;
    const int NE = CPG * NTOK;     // 65536
    const size_t base = ((size_t)bb * CCH + (size_t)g * CPG) * NTOK;
    const int t = threadIdx.x;

    float s = 0.f, ss = 0.f;
    for (int i = t * 4; i < NE; i += 4096) {
        float4 v = *reinterpret_cast<const float4*>(&x[base + i]);
        s  += v.x + v.y + v.z + v.w;
        ss += v.x * v.x + v.y * v.y + v.z * v.z + v.w * v.w;
    }
    __shared__ float sh[1024], sh2[1024];
    sh[t] = s; sh2[t] = ss;
    __syncthreads();
    for (int o = 512; o > 0; o >>= 1) {
        if (t < o) { sh[t] += sh[t + o]; sh2[t] += sh2[t + o]; }
        __syncthreads();
    }
    const float mu   = sh[0] / (float)NE;
    const float var  = sh2[0] / (float)NE - mu * mu;
    const float rstd = rsqrtf(var + EPSV);

    __shared__ float ts[16][65];
    const int c_l = t >> 6;
    const int n_l = t & 63;
    const int c   = g * CPG + c_l;
    const float sc = rstd * w[c];
    const float sb = b[c] - mu * sc;
    const int wn = t >> 4;
    const int wc = t & 15;
    __half* dst = g_hn + (size_t)bb * NTOK * CCH + g * CPG;

    for (int n0 = 0; n0 < NTOK; n0 += 64) {
        ts[c_l][n_l] = x[base + (size_t)c_l * NTOK + n0 + n_l] * sc + sb;
        __syncthreads();
        dst[(size_t)(n0 + wn) * CCH + wc] = __float2half_rn(ts[wc][wn]);
        __syncthreads();
    }
}

// ---------------------------------------------------------------
// Row softmax: fp16 in-place over g_p. One block per row.
// ---------------------------------------------------------------
__global__ void softmax_kernel()
{
    const size_t row = blockIdx.x;
    __half* p = g_p + row * (size_t)NTOK;
    const int t = threadIdx.x;

    float loc[16];
    float mx = -1e30f;
#pragma unroll
    for (int i = 0; i < 4; i++) {
        uint2 u = *reinterpret_cast<const uint2*>(&p[t * 4 + i * 1024]);
        __half2 h0, h1;
        memcpy(&h0, &u.x, 4); memcpy(&h1, &u.y, 4);
        float2 f0 = __half22float2(h0), f1 = __half22float2(h1);
        loc[4*i] = f0.x; loc[4*i+1] = f0.y; loc[4*i+2] = f1.x; loc[4*i+3] = f1.y;
        mx = fmaxf(mx, fmaxf(fmaxf(f0.x, f0.y), fmaxf(f1.x, f1.y)));
    }
    __shared__ float sh[256];
    sh[t] = mx; __syncthreads();
    for (int o = 128; o > 0; o >>= 1) {
        if (t < o) sh[t] = fmaxf(sh[t], sh[t + o]);
        __syncthreads();
    }
    mx = sh[0];
    __syncthreads();

    float sum = 0.f;
#pragma unroll
    for (int i = 0; i < 16; i++) {
        loc[i] = __expf(loc[i] - mx);
        sum += loc[i];
    }
    sh[t] = sum; __syncthreads();
    for (int o = 128; o > 0; o >>= 1) {
        if (t < o) sh[t] += sh[t + o];
        __syncthreads();
    }
    const float inv = 1.0f / sh[0];
#pragma unroll
    for (int i = 0; i < 4; i++) {
        __half2 h0 = __floats2half2_rn(loc[4*i] * inv,   loc[4*i+1] * inv);
        __half2 h1 = __floats2half2_rn(loc[4*i+2] * inv, loc[4*i+3] * inv);
        uint2 u = make_uint2(h2_bits(h0), h2_bits(h1));
        *reinterpret_cast<uint2*>(&p[t * 4 + i * 1024]) = u;
    }
}

// ---------------------------------------------------------------
// fp16 GEMM body: CTA tile 128x256x64, 3-stage cp.async ring,
// 8 warps (2m x 4n), warp tile 64x64 (4x8 m16n8k16).
//   C[m,n] = scale * sum_k A[m,k]*B[n,k] (+epi)
// EPI: 0 none | 1 +bias[n] | 2 +bias[m]+resid[m*Nn+n]
// OUTT: 0 fp32 | 1 fp16 | 2 fp16 transposed C[n*M+m]
// A, B, C, resid already batch-offset. B ld = K. bias indexed by
// LOCAL n (n0 + offset) for EPI=1, global m for EPI=2.
// ---------------------------------------------------------------
template<int EPI, int OUTT>
__device__ __forceinline__ void gemm_body(
    char* smem, const __half* __restrict__ A, const __half* __restrict__ B,
    void* __restrict__ Cv, int M, int Nn, int K, int m0, int n0,
    const float* __restrict__ bias, const float* __restrict__ resid, float scale)
{
    const uint32_t sbase = smem_u32(smem);
    const int tid = threadIdx.x, wid = tid >> 5, lane = tid & 31;
    const int wm = (wid & 1) * 64;
    const int wn = (wid >> 1) * 64;
    const int g = lane >> 2, tg = lane & 3;

    float acc[4][8][4] = {};

    auto stage = [&](int buf, int k0) {
        char* da = smem + buf * STAGE_BYTES;
        char* db = da + 16384;
#pragma unroll
        for (int i = 0; i < 4; i++) {           // A: 128 rows x 64 k
            int cid = tid + i * 256;
            int r = cid >> 3, c = cid & 7;
            uint32_t off = (uint32_t)(r * 128 + c * 16) ^ (uint32_t)((r & 7) << 4);
            cp16(da + off, A + (size_t)(m0 + r) * K + k0 + c * 8);
        }
#pragma unroll
        for (int i = 0; i < 8; i++) {           // B: 256 rows x 64 k
            int cid = tid + i * 256;
            int r = cid >> 3, c = cid & 7;
            uint32_t off = (uint32_t)(r * 128 + c * 16) ^ (uint32_t)((r & 7) << 4);
            cp16(db + off, B + (size_t)(n0 + r) * K + k0 + c * 8);
        }
    };

    const int lrowA = lane & 15;
    const int coffA = lane >> 4;
    const int browB = ((lane >> 4) << 3) + (lane & 7);
    const int bcoB  = (lane >> 3) & 1;
    const uint32_t swz = (uint32_t)((lane & 7) << 4);

    const int KT = K >> 6;
    stage(0, 0);  CP_COMMIT();
    stage(1, 64); CP_COMMIT();

    for (int kt = 0; kt < KT; kt++) {
        asm volatile("cp.async.wait_group 1;");
        __syncthreads();
        if (kt + 2 < KT) stage((kt + 2) % 3, (kt + 2) * 64);
        CP_COMMIT();

        const uint32_t abase = sbase + (kt % 3) * STAGE_BYTES;
        const uint32_t bbase = abase + 16384;

#pragma unroll
        for (int ks = 0; ks < 4; ks++) {
            uint32_t bf[8][2];
#pragma unroll
            for (int jr = 0; jr < 4; jr++) {
                uint32_t addr = bbase + (uint32_t)((wn + browB + 16 * jr) * 128)
                              + (((uint32_t)((ks * 2 + bcoB) * 16)) ^ swz);
                LDSM4(bf[2*jr][0], bf[2*jr][1], bf[2*jr+1][0], bf[2*jr+1][1], addr);
            }
#pragma unroll
            for (int i = 0; i < 4; i++) {
                uint32_t a[4];
                uint32_t addr = abase + (uint32_t)((wm + 16 * i + lrowA) * 128)
                              + (((uint32_t)((ks * 2 + coffA) * 16)) ^ swz);
                LDSM4(a[0], a[1], a[2], a[3], addr);
#pragma unroll
                for (int j = 0; j < 8; j++)
                    mma_f16(acc[i][j], a, bf[j]);
            }
        }
    }

    // ---------------- epilogue ----------------
    if (OUTT == 0) {
        float* C = (float*)Cv;
#pragma unroll
        for (int i = 0; i < 4; i++) {
            const int m = m0 + wm + 16 * i + g;
#pragma unroll
            for (int j = 0; j < 8; j++) {
                const int n = n0 + wn + 8 * j + 2 * tg;
                float v0 = acc[i][j][0] * scale, v1 = acc[i][j][1] * scale;
                float v2 = acc[i][j][2] * scale, v3 = acc[i][j][3] * scale;
                if (EPI == 1) { v0 += bias[n]; v1 += bias[n+1]; v2 += bias[n]; v3 += bias[n+1]; }
                if (EPI == 2) {
                    const float* r0 = resid + (size_t)m * Nn + n;
                    const float* r1 = resid + (size_t)(m + 8) * Nn + n;
                    v0 += bias[m] + r0[0];     v1 += bias[m] + r0[1];
                    v2 += bias[m + 8] + r1[0]; v3 += bias[m + 8] + r1[1];
                }
                *reinterpret_cast<float2*>(&C[(size_t)m * Nn + n])       = make_float2(v0, v1);
                *reinterpret_cast<float2*>(&C[(size_t)(m + 8) * Nn + n]) = make_float2(v2, v3);
            }
        }
    } else if (OUTT == 1) {
        __half* C = (__half*)Cv;
#pragma unroll
        for (int i = 0; i < 4; i++) {
            const int m = m0 + wm + 16 * i + g;
#pragma unroll
            for (int j = 0; j < 8; j++) {
                const int n = n0 + wn + 8 * j + 2 * tg;
                float v0 = acc[i][j][0] * scale, v1 = acc[i][j][1] * scale;
                float v2 = acc[i][j][2] * scale, v3 = acc[i][j][3] * scale;
                if (EPI == 1) { v0 += bias[n]; v1 += bias[n+1]; v2 += bias[n]; v3 += bias[n+1]; }
                *reinterpret_cast<__half2*>(&C[(size_t)m * Nn + n])       = __floats2half2_rn(v0, v1);
                *reinterpret_cast<__half2*>(&C[(size_t)(m + 8) * Nn + n]) = __floats2half2_rn(v2, v3);
            }
        }
    } else {
        // transposed fp16: C[n*M + m]; per-warp 64n x 64m smem transpose (8KB)
        __half* C = (__half*)Cv;
        __syncthreads();
        char* tp = smem + wid * 8192;
#pragma unroll
        for (int i = 0; i < 4; i++) {
#pragma unroll
            for (int j = 0; j < 8; j++) {
                const int nl = 8 * j + 2 * tg;
                const int nch = n0 + wn + nl;
                float v0 = acc[i][j][0] * scale, v1 = acc[i][j][1] * scale;
                float v2 = acc[i][j][2] * scale, v3 = acc[i][j][3] * scale;
                if (EPI == 1) { v0 += bias[nch]; v1 += bias[nch+1]; v2 += bias[nch]; v3 += bias[nch+1]; }
                const int ml0 = 16 * i + g, ml1 = ml0 + 8;
                auto put = [&](int nn, int mm, float vv) {
                    uint32_t o = (uint32_t)(nn * 128 + ((((mm >> 3) ^ (nn & 7)) << 4)) + (mm & 7) * 2);
                    *reinterpret_cast<__half*>(tp + o) = __float2half_rn(vv);
                };
                put(nl,     ml0, v0); put(nl + 1, ml0, v1);
                put(nl,     ml1, v2); put(nl + 1, ml1, v3);
            }
        }
        __syncwarp();
#pragma unroll
        for (int r = 0; r < 64; r++) {
            uint32_t o = (uint32_t)(r * 128 + (((lane >> 2) ^ (r & 7)) << 4) + (lane & 3) * 4);
            uint32_t v = *reinterpret_cast<uint32_t*>(tp + o);
            *reinterpret_cast<uint32_t*>(&C[(size_t)(n0 + wn + r) * M + m0 + wm + lane * 2]) = v;
        }
    }
}

// ---------------------------------------------------------------
template<int EPI, int OUTT>
__global__ void __launch_bounds__(256, 1)
hgemm(const __half* __restrict__ A, const __half* __restrict__ B,
      void* __restrict__ Cv, int M, int Nn, int K,
      size_t sA, size_t sB, size_t sCe,
      const float* __restrict__ bias,
      const float* __restrict__ resid, size_t sR, float scale)
{
    extern __shared__ __align__(1024) char smem[];
    const int bz = blockIdx.z;
    char* cptr = (OUTT == 0)
        ? (char*)((float*)Cv + (size_t)bz * sCe)
        : (char*)((__half*)Cv + (size_t)bz * sCe);
    gemm_body<EPI, OUTT>(smem, A + (size_t)bz * sA, B + (size_t)bz * sB,
                         cptr, M, Nn, K, blockIdx.y * BM, blockIdx.x * BN,
                         bias, resid ? resid + (size_t)bz * sR : nullptr, scale);
}

// Fused QKV: grid.x = 6 (proj*2 + half), grid.y = 32, grid.z = BATCH
__global__ void __launch_bounds__(256, 1)
qkv_gemm(const __half* __restrict__ hn,
         const float* __restrict__ bq, const float* __restrict__ bk,
         const float* __restrict__ bv,
         __half* __restrict__ q, __half* __restrict__ k, __half* __restrict__ v)
{
    extern __shared__ __align__(1024) char smem[];
    const int p    = blockIdx.x >> 1;
    const int half = blockIdx.x & 1;
    const int bb   = blockIdx.z;
    const size_t sTok = (size_t)NTOK * CCH;
    const size_t sChn = (size_t)CCH * NTOK;
    const __half* W  = g_w16 + (size_t)p * CCH * CCH;
    const float* bi  = (p == 0) ? bq : (p == 1) ? bk : bv;
    const __half* A  = hn + (size_t)bb * sTok;
    const int m0 = blockIdx.y * BM, n0 = half * BN;

    if (p < 2) {
        __half* C = ((p == 0) ? q : k) + (size_t)bb * sTok;
        gemm_body<1, 1>(smem, A, W, C, NTOK, CCH, CCH, m0, n0, bi, nullptr, 1.0f);
    } else {
        __half* C = v + (size_t)bb * sChn;
        gemm_body<1, 2>(smem, A, W, C, NTOK, CCH, CCH, m0, n0, bi, nullptr, 1.0f);
    }
}

// ---------------------------------------------------------------
extern "C" void kernel_launch(void* const* d_in, const int* in_sizes, int n_in,
                              void* d_out, int out_size)
{
    const float* x    = (const float*)d_in[0];
    const float* gn_w = (const float*)d_in[1];
    const float* gn_b = (const float*)d_in[2];
    const float* wq   = (const float*)d_in[3];
    const float* bq   = (const float*)d_in[4];
    const float* wk   = (const float*)d_in[5];
    const float* bk   = (const float*)d_in[6];
    const float* wv   = (const float*)d_in[7];
    const float* bv   = (const float*)d_in[8];
    const float* wo   = (const float*)d_in[9];
    const float* bo   = (const float*)d_in[10];
    float* out = (float*)d_out;

    __half *hn, *q, *k, *vt, *o, *p, *w16;
    cudaGetSymbolAddress((void**)&hn, g_hn);
    cudaGetSymbolAddress((void**)&q,  g_q);
    cudaGetSymbolAddress((void**)&k,  g_k);
    cudaGetSymbolAddress((void**)&vt, g_vt);
    cudaGetSymbolAddress((void**)&o,  g_o);
    cudaGetSymbolAddress((void**)&p,  g_p);
    cudaGetSymbolAddress((void**)&w16, g_w16);
    const __half* wo16 = w16 + 3 * (size_t)CCH * CCH;

    const size_t sTok = (size_t)NTOK * CCH;
    const size_t sChn = (size_t)CCH * NTOK;
    const size_t sAtt = (size_t)NTOK * NTOK;
    const float att_scale = 1.0f / sqrtf((float)CCH);

    cudaFuncSetAttribute(qkv_gemm,    cudaFuncAttributeMaxDynamicSharedMemorySize, DSMEM);
    cudaFuncSetAttribute(hgemm<0, 1>, cudaFuncAttributeMaxDynamicSharedMemorySize, DSMEM);
    cudaFuncSetAttribute(hgemm<2, 0>, cudaFuncAttributeMaxDynamicSharedMemorySize, DSMEM);

    // 0) weights -> fp16
    convw_kernel<<<dim3(CCH * CCH / 1024, 4), 256>>>(wq, wk, wv, wo);

    // 1) GroupNorm -> g_hn [b, n, c] fp16 (transposed)
    groupnorm_kernel<<<BATCH * GRP, 1024>>>(x, gn_w, gn_b);

    // 2) fused QKV (V transposed)
    qkv_gemm<<<dim3(6, NTOK / BM, BATCH), 256, DSMEM>>>(hn, bq, bk, bv, q, k, vt);

    // 3) S = scale * Q K^T  -> g_p (fp16)
    hgemm<0, 1><<<dim3(NTOK / BN, NTOK / BM, BATCH), 256, DSMEM>>>(
        q, k, p, NTOK, NTOK, CCH, sTok, sTok, sAtt, nullptr, nullptr, 0, att_scale);

    // 4) softmax in-place on g_p
    softmax_kernel<<<BATCH * NTOK, 256>>>();

    // 5) O = P V
    hgemm<0, 1><<<dim3(CCH / BN, NTOK / BM, BATCH), 256, DSMEM>>>(
        p, vt, o, NTOK, CCH, NTOK, sAtt, sChn, sTok, nullptr, nullptr, 0, 1.0f);

    // 6) out[b,c,n] = x + bo[c] + wo @ O^T
    hgemm<2, 0><<<dim3(NTOK / BN, CCH / BM, BATCH), 256, DSMEM>>>(
        wo16, o, out, CCH, NTOK, CCH, 0, sTok, sChn, bo, x, sChn, 1.0f);
}

// round 9
// speedup vs baseline: 8.0202x; 1.0086x over previous
#include <cuda_runtime.h>
#include <cuda_fp16.h>
#include <math.h>
#include <stdint.h>

#define BATCH 2
#define CCH   512
#define NTOK  4096
#define GRP   32
#define CPG   (CCH / GRP)
#define EPSV  1e-6f

// GEMM tiling
#define BM 128
#define BN 256
#define BK 128
#define A_BYTES (BM * BK * 2)          // 32768
#define B_BYTES (BN * BK * 2)          // 65536
#define STAGE_BYTES (A_BYTES + B_BYTES)
#define DSMEM (2 * STAGE_BYTES)        // 196608

// -------- scratch (__device__ globals; no allocation allowed) --------
__device__ __half g_hn[(size_t)BATCH * NTOK * CCH];   // GN out, TRANSPOSED [b, n, c]
__device__ __half g_q [(size_t)BATCH * NTOK * CCH];   // [b, n, c]
__device__ __half g_k [(size_t)BATCH * NTOK * CCH];   // [b, n, c]
__device__ __half g_vt[(size_t)BATCH * CCH * NTOK];   // V TRANSPOSED [b, c, n]
__device__ __half g_o [(size_t)BATCH * NTOK * CCH];   // [b, n, c]
__device__ __half g_p [(size_t)BATCH * NTOK * NTOK];  // scores -> probs (fp16, in-place)
__device__ __half g_w16[4 * (size_t)CCH * CCH];       // wq, wk, wv, wo in fp16

// ---------------- helpers ----------------
__device__ __forceinline__ uint32_t smem_u32(const void* p) {
    uint32_t a;
    asm("{ .reg .u64 t; cvta.to.shared.u64 t, %1; cvt.u32.u64 %0, t; }"
        : "=r"(a) : "l"(p));
    return a;
}
__device__ __forceinline__ void cp16(void* dst, const void* src) {
    uint32_t d = smem_u32(dst);
    asm volatile("cp.async.cg.shared.global [%0], [%1], 16;" :: "r"(d), "l"(src));
}
#define CP_COMMIT() asm volatile("cp.async.commit_group;")

#define LDSM4(r0, r1, r2, r3, addr) \
    asm volatile("ldmatrix.sync.aligned.m8n8.x4.shared.b16 {%0,%1,%2,%3}, [%4];" \
        : "=r"(r0), "=r"(r1), "=r"(r2), "=r"(r3) : "r"(addr))

__device__ __forceinline__ void mma_f16(float* d, const uint32_t* a, const uint32_t* b) {
    asm volatile(
        "mma.sync.aligned.m16n8k16.row.col.f32.f16.f16.f32 "
        "{%0,%1,%2,%3},{%4,%5,%6,%7},{%8,%9},{%0,%1,%2,%3};"
        : "+f"(d[0]), "+f"(d[1]), "+f"(d[2]), "+f"(d[3])
        : "r"(a[0]), "r"(a[1]), "r"(a[2]), "r"(a[3]), "r"(b[0]), "r"(b[1]));
}

__device__ __forceinline__ uint32_t h2_bits(__half2 h) {
    uint32_t u;
    memcpy(&u, &h, 4);
    return u;
}

// ---------------------------------------------------------------
// Weight conversion fp32 -> fp16
// ---------------------------------------------------------------
__global__ void convw_kernel(const float* __restrict__ a, const float* __restrict__ b,
                             const float* __restrict__ c, const float* __restrict__ d)
{
    const float* srcs[4] = {a, b, c, d};
    const float* src = srcs[blockIdx.y];
    __half* dst = g_w16 + (size_t)blockIdx.y * CCH * CCH;
    int i = (blockIdx.x * 256 + threadIdx.x) * 4;
    float4 v = *reinterpret_cast<const float4*>(&src[i]);
    *reinterpret_cast<__half2*>(&dst[i])     = __floats2half2_rn(v.x, v.y);
    *reinterpret_cast<__half2*>(&dst[i + 2]) = __floats2half2_rn(v.z, v.w);
}

// ---------------------------------------------------------------
// GroupNorm + transpose: one block (1024 thr) per (batch, group).
// ---------------------------------------------------------------
__global__ void groupnorm_kernel(const float* __restrict__ x,
                                 const float* __restrict__ w,
                                 const float* __restrict__ b)
{
    const int bg = blockIdx.x;
    const int bb = bg / GRP;
    const int g  = bg % GRP;
    const int NE = CPG * NTOK;     // 65536
    const size_t base = ((size_t)bb * CCH + (size_t)g * CPG) * NTOK;
    const int t = threadIdx.x;

    float s = 0.f, ss = 0.f;
    for (int i = t * 4; i < NE; i += 4096) {
        float4 v = *reinterpret_cast<const float4*>(&x[base + i]);
        s  += v.x + v.y + v.z + v.w;
        ss += v.x * v.x + v.y * v.y + v.z * v.z + v.w * v.w;
    }
    __shared__ float sh[1024], sh2[1024];
    sh[t] = s; sh2[t] = ss;
    __syncthreads();
    for (int o = 512; o > 0; o >>= 1) {
        if (t < o) { sh[t] += sh[t + o]; sh2[t] += sh2[t + o]; }
        __syncthreads();
    }
    const float mu   = sh[0] / (float)NE;
    const float var  = sh2[0] / (float)NE - mu * mu;
    const float rstd = rsqrtf(var + EPSV);

    __shared__ float ts[16][65];
    const int c_l = t >> 6;
    const int n_l = t & 63;
    const int c   = g * CPG + c_l;
    const float sc = rstd * w[c];
    const float sb = b[c] - mu * sc;
    const int wn = t >> 4;
    const int wc = t & 15;
    __half* dst = g_hn + (size_t)bb * NTOK * CCH + g * CPG;

    for (int n0 = 0; n0 < NTOK; n0 += 64) {
        ts[c_l][n_l] = x[base + (size_t)c_l * NTOK + n0 + n_l] * sc + sb;
        __syncthreads();
        dst[(size_t)(n0 + wn) * CCH + wc] = __float2half_rn(ts[wc][wn]);
        __syncthreads();
    }
}

// ---------------------------------------------------------------
// Row softmax: fp16 in-place over g_p. One block per row.
// ---------------------------------------------------------------
__global__ void softmax_kernel()
{
    const size_t row = blockIdx.x;
    __half* p = g_p + row * (size_t)NTOK;
    const int t = threadIdx.x;

    float loc[16];
    float mx = -1e30f;
#pragma unroll
    for (int i = 0; i < 4; i++) {
        uint2 u = *reinterpret_cast<const uint2*>(&p[t * 4 + i * 1024]);
        __half2 h0, h1;
        memcpy(&h0, &u.x, 4); memcpy(&h1, &u.y, 4);
        float2 f0 = __half22float2(h0), f1 = __half22float2(h1);
        loc[4*i] = f0.x; loc[4*i+1] = f0.y; loc[4*i+2] = f1.x; loc[4*i+3] = f1.y;
        mx = fmaxf(mx, fmaxf(fmaxf(f0.x, f0.y), fmaxf(f1.x, f1.y)));
    }
    __shared__ float sh[256];
    sh[t] = mx; __syncthreads();
    for (int o = 128; o > 0; o >>= 1) {
        if (t < o) sh[t] = fmaxf(sh[t], sh[t + o]);
        __syncthreads();
    }
    mx = sh[0];
    __syncthreads();

    float sum = 0.f;
#pragma unroll
    for (int i = 0; i < 16; i++) {
        loc[i] = __expf(loc[i] - mx);
        sum += loc[i];
    }
    sh[t] = sum; __syncthreads();
    for (int o = 128; o > 0; o >>= 1) {
        if (t < o) sh[t] += sh[t + o];
        __syncthreads();
    }
    const float inv = 1.0f / sh[0];
#pragma unroll
    for (int i = 0; i < 4; i++) {
        __half2 h0 = __floats2half2_rn(loc[4*i] * inv,   loc[4*i+1] * inv);
        __half2 h1 = __floats2half2_rn(loc[4*i+2] * inv, loc[4*i+3] * inv);
        uint2 u = make_uint2(h2_bits(h0), h2_bits(h1));
        *reinterpret_cast<uint2*>(&p[t * 4 + i * 1024]) = u;
    }
}

// ---------------------------------------------------------------
// fp16 GEMM body: CTA tile 128x256x128, 2-stage cp.async double
// buffer, 8 warps (2m x 4n), warp tile 64x64 (4x8 m16n8k16).
// smem rows are 256B (BK=128 fp16) with 128B-XOR swizzle.
//   C[m,n] = scale * sum_k A[m,k]*B[n,k] (+epi)
// EPI: 0 none | 1 +bias[n] | 2 +bias[m]+resid[m*Nn+n]
// OUTT: 0 fp32 | 1 fp16 | 2 fp16 transposed C[n*M+m]
// ---------------------------------------------------------------
template<int EPI, int OUTT>
__device__ __forceinline__ void gemm_body(
    char* smem, const __half* __restrict__ A, const __half* __restrict__ B,
    void* __restrict__ Cv, int M, int Nn, int K, int m0, int n0,
    const float* __restrict__ bias, const float* __restrict__ resid, float scale)
{
    const uint32_t sbase = smem_u32(smem);
    const int tid = threadIdx.x, wid = tid >> 5, lane = tid & 31;
    const int wm = (wid & 1) * 64;
    const int wn = (wid >> 1) * 64;
    const int g = lane >> 2, tg = lane & 3;

    float acc[4][8][4] = {};

    auto stage = [&](int buf, int k0) {
        char* da = smem + buf * STAGE_BYTES;
        char* db = da + A_BYTES;
#pragma unroll
        for (int i = 0; i < 8; i++) {           // A: 128 rows x 256B
            int cid = tid + i * 256;
            int r = cid >> 4, c = cid & 15;
            uint32_t off = (uint32_t)(r * 256 + c * 16) ^ (uint32_t)((r & 7) << 4);
            cp16(da + off, A + (size_t)(m0 + r) * K + k0 + c * 8);
        }
#pragma unroll
        for (int i = 0; i < 16; i++) {          // B: 256 rows x 256B
            int cid = tid + i * 256;
            int r = cid >> 4, c = cid & 15;
            uint32_t off = (uint32_t)(r * 256 + c * 16) ^ (uint32_t)((r & 7) << 4);
            cp16(db + off, B + (size_t)(n0 + r) * K + k0 + c * 8);
        }
    };

    const int lrowA = lane & 15;
    const int coffA = lane >> 4;
    const int browB = ((lane >> 4) << 3) + (lane & 7);
    const int bcoB  = (lane >> 3) & 1;
    const uint32_t swz = (uint32_t)((lane & 7) << 4);

    const int KT = K / BK;
    stage(0, 0);  CP_COMMIT();

    for (int kt = 0; kt < KT; kt++) {
        if (kt + 1 < KT) stage((kt + 1) & 1, (kt + 1) * BK);
        CP_COMMIT();
        asm volatile("cp.async.wait_group 1;");
        __syncthreads();

        const uint32_t abase = sbase + (kt & 1) * STAGE_BYTES;
        const uint32_t bbase = abase + A_BYTES;

#pragma unroll
        for (int ks = 0; ks < 8; ks++) {
            uint32_t bf[8][2];
#pragma unroll
            for (int jr = 0; jr < 4; jr++) {
                uint32_t addr = bbase + (uint32_t)((wn + browB + 16 * jr) * 256)
                              + (((uint32_t)((ks * 2 + bcoB) * 16)) ^ swz);
                LDSM4(bf[2*jr][0], bf[2*jr][1], bf[2*jr+1][0], bf[2*jr+1][1], addr);
            }
#pragma unroll
            for (int i = 0; i < 4; i++) {
                uint32_t a[4];
                uint32_t addr = abase + (uint32_t)((wm + 16 * i + lrowA) * 256)
                              + (((uint32_t)((ks * 2 + coffA) * 16)) ^ swz);
                LDSM4(a[0], a[1], a[2], a[3], addr);
#pragma unroll
                for (int j = 0; j < 8; j++)
                    mma_f16(acc[i][j], a, bf[j]);
            }
        }
        __syncthreads();
    }

    // ---------------- epilogue ----------------
    if (OUTT == 0) {
        float* C = (float*)Cv;
#pragma unroll
        for (int i = 0; i < 4; i++) {
            const int m = m0 + wm + 16 * i + g;
#pragma unroll
            for (int j = 0; j < 8; j++) {
                const int n = n0 + wn + 8 * j + 2 * tg;
                float v0 = acc[i][j][0] * scale, v1 = acc[i][j][1] * scale;
                float v2 = acc[i][j][2] * scale, v3 = acc[i][j][3] * scale;
                if (EPI == 1) { v0 += bias[n]; v1 += bias[n+1]; v2 += bias[n]; v3 += bias[n+1]; }
                if (EPI == 2) {
                    const float* r0 = resid + (size_t)m * Nn + n;
                    const float* r1 = resid + (size_t)(m + 8) * Nn + n;
                    v0 += bias[m] + r0[0];     v1 += bias[m] + r0[1];
                    v2 += bias[m + 8] + r1[0]; v3 += bias[m + 8] + r1[1];
                }
                *reinterpret_cast<float2*>(&C[(size_t)m * Nn + n])       = make_float2(v0, v1);
                *reinterpret_cast<float2*>(&C[(size_t)(m + 8) * Nn + n]) = make_float2(v2, v3);
            }
        }
    } else if (OUTT == 1) {
        __half* C = (__half*)Cv;
#pragma unroll
        for (int i = 0; i < 4; i++) {
            const int m = m0 + wm + 16 * i + g;
#pragma unroll
            for (int j = 0; j < 8; j++) {
                const int n = n0 + wn + 8 * j + 2 * tg;
                float v0 = acc[i][j][0] * scale, v1 = acc[i][j][1] * scale;
                float v2 = acc[i][j][2] * scale, v3 = acc[i][j][3] * scale;
                if (EPI == 1) { v0 += bias[n]; v1 += bias[n+1]; v2 += bias[n]; v3 += bias[n+1]; }
                *reinterpret_cast<__half2*>(&C[(size_t)m * Nn + n])       = __floats2half2_rn(v0, v1);
                *reinterpret_cast<__half2*>(&C[(size_t)(m + 8) * Nn + n]) = __floats2half2_rn(v2, v3);
            }
        }
    } else {
        // transposed fp16: C[n*M + m]; per-warp 64n x 64m smem transpose (8KB)
        __half* C = (__half*)Cv;
        __syncthreads();
        char* tp = smem + wid * 8192;
#pragma unroll
        for (int i = 0; i < 4; i++) {
#pragma unroll
            for (int j = 0; j < 8; j++) {
                const int nl = 8 * j + 2 * tg;
                const int nch = n0 + wn + nl;
                float v0 = acc[i][j][0] * scale, v1 = acc[i][j][1] * scale;
                float v2 = acc[i][j][2] * scale, v3 = acc[i][j][3] * scale;
                if (EPI == 1) { v0 += bias[nch]; v1 += bias[nch+1]; v2 += bias[nch]; v3 += bias[nch+1]; }
                const int ml0 = 16 * i + g, ml1 = ml0 + 8;
                auto put = [&](int nn, int mm, float vv) {
                    uint32_t o = (uint32_t)(nn * 128 + ((((mm >> 3) ^ (nn & 7)) << 4)) + (mm & 7) * 2);
                    *reinterpret_cast<__half*>(tp + o) = __float2half_rn(vv);
                };
                put(nl,     ml0, v0); put(nl + 1, ml0, v1);
                put(nl,     ml1, v2); put(nl + 1, ml1, v3);
            }
        }
        __syncwarp();
#pragma unroll
        for (int r = 0; r < 64; r++) {
            uint32_t o = (uint32_t)(r * 128 + (((lane >> 2) ^ (r & 7)) << 4) + (lane & 3) * 4);
            uint32_t v = *reinterpret_cast<uint32_t*>(tp + o);
            *reinterpret_cast<uint32_t*>(&C[(size_t)(n0 + wn + r) * M + m0 + wm + lane * 2]) = v;
        }
    }
}

// ---------------------------------------------------------------
template<int EPI, int OUTT>
__global__ void __launch_bounds__(256, 1)
hgemm(const __half* __restrict__ A, const __half* __restrict__ B,
      void* __restrict__ Cv, int M, int Nn, int K,
      size_t sA, size_t sB, size_t sCe,
      const float* __restrict__ bias,
      const float* __restrict__ resid, size_t sR, float scale)
{
    extern __shared__ __align__(1024) char smem[];
    const int bz = blockIdx.z;
    char* cptr = (OUTT == 0)
        ? (char*)((float*)Cv + (size_t)bz * sCe)
        : (char*)((__half*)Cv + (size_t)bz * sCe);
    gemm_body<EPI, OUTT>(smem, A + (size_t)bz * sA, B + (size_t)bz * sB,
                         cptr, M, Nn, K, blockIdx.y * BM, blockIdx.x * BN,
                         bias, resid ? resid + (size_t)bz * sR : nullptr, scale);
}

// Fused QKV: grid.x = 6 (proj*2 + half), grid.y = 32, grid.z = BATCH
__global__ void __launch_bounds__(256, 1)
qkv_gemm(const __half* __restrict__ hn,
         const float* __restrict__ bq, const float* __restrict__ bk,
         const float* __restrict__ bv,
         __half* __restrict__ q, __half* __restrict__ k, __half* __restrict__ v)
{
    extern __shared__ __align__(1024) char smem[];
    const int p    = blockIdx.x >> 1;
    const int half = blockIdx.x & 1;
    const int bb   = blockIdx.z;
    const size_t sTok = (size_t)NTOK * CCH;
    const size_t sChn = (size_t)CCH * NTOK;
    const __half* W  = g_w16 + (size_t)p * CCH * CCH;
    const float* bi  = (p == 0) ? bq : (p == 1) ? bk : bv;
    const __half* A  = hn + (size_t)bb * sTok;
    const int m0 = blockIdx.y * BM, n0 = half * BN;

    if (p < 2) {
        __half* C = ((p == 0) ? q : k) + (size_t)bb * sTok;
        gemm_body<1, 1>(smem, A, W, C, NTOK, CCH, CCH, m0, n0, bi, nullptr, 1.0f);
    } else {
        __half* C = v + (size_t)bb * sChn;
        gemm_body<1, 2>(smem, A, W, C, NTOK, CCH, CCH, m0, n0, bi, nullptr, 1.0f);
    }
}

// ---------------------------------------------------------------
extern "C" void kernel_launch(void* const* d_in, const int* in_sizes, int n_in,
                              void* d_out, int out_size)
{
    const float* x    = (const float*)d_in[0];
    const float* gn_w = (const float*)d_in[1];
    const float* gn_b = (const float*)d_in[2];
    const float* wq   = (const float*)d_in[3];
    const float* bq   = (const float*)d_in[4];
    const float* wk   = (const float*)d_in[5];
    const float* bk   = (const float*)d_in[6];
    const float* wv   = (const float*)d_in[7];
    const float* bv   = (const float*)d_in[8];
    const float* wo   = (const float*)d_in[9];
    const float* bo   = (const float*)d_in[10];
    float* out = (float*)d_out;

    __half *hn, *q, *k, *vt, *o, *p, *w16;
    cudaGetSymbolAddress((void**)&hn, g_hn);
    cudaGetSymbolAddress((void**)&q,  g_q);
    cudaGetSymbolAddress((void**)&k,  g_k);
    cudaGetSymbolAddress((void**)&vt, g_vt);
    cudaGetSymbolAddress((void**)&o,  g_o);
    cudaGetSymbolAddress((void**)&p,  g_p);
    cudaGetSymbolAddress((void**)&w16, g_w16);
    const __half* wo16 = w16 + 3 * (size_t)CCH * CCH;

    const size_t sTok = (size_t)NTOK * CCH;
    const size_t sChn = (size_t)CCH * NTOK;
    const size_t sAtt = (size_t)NTOK * NTOK;
    const float att_scale = 1.0f / sqrtf((float)CCH);

    cudaFuncSetAttribute(qkv_gemm,    cudaFuncAttributeMaxDynamicSharedMemorySize, DSMEM);
    cudaFuncSetAttribute(hgemm<0, 1>, cudaFuncAttributeMaxDynamicSharedMemorySize, DSMEM);
    cudaFuncSetAttribute(hgemm<2, 0>, cudaFuncAttributeMaxDynamicSharedMemorySize, DSMEM);

    // 0) weights -> fp16
    convw_kernel<<<dim3(CCH * CCH / 1024, 4), 256>>>(wq, wk, wv, wo);

    // 1) GroupNorm -> g_hn [b, n, c] fp16 (transposed)
    groupnorm_kernel<<<BATCH * GRP, 1024>>>(x, gn_w, gn_b);

    // 2) fused QKV (V transposed)
    qkv_gemm<<<dim3(6, NTOK / BM, BATCH), 256, DSMEM>>>(hn, bq, bk, bv, q, k, vt);

    // 3) S = scale * Q K^T  -> g_p (fp16)
    hgemm<0, 1><<<dim3(NTOK / BN, NTOK / BM, BATCH), 256, DSMEM>>>(
        q, k, p, NTOK, NTOK, CCH, sTok, sTok, sAtt, nullptr, nullptr, 0, att_scale);

    // 4) softmax in-place on g_p
    softmax_kernel<<<BATCH * NTOK, 256>>>();

    // 5) O = P V
    hgemm<0, 1><<<dim3(CCH / BN, NTOK / BM, BATCH), 256, DSMEM>>>(
        p, vt, o, NTOK, CCH, NTOK, sAtt, sChn, sTok, nullptr, nullptr, 0, 1.0f);

    // 6) out[b,c,n] = x + bo[c] + wo @ O^T
    hgemm<2, 0><<<dim3(NTOK / BN, CCH / BM, BATCH), 256, DSMEM>>>(
        wo16, o, out, CCH, NTOK, CCH, 0, sTok, sChn, bo, x, sChn, 1.0f);
}